// round 5
// baseline (speedup 1.0000x reference)
#include <cuda_runtime.h>
#include <cuda_bf16.h>
#include <cstdint>
#include <math.h>

// ---------------- problem constants ----------------
#define SEQ   2048
#define HID   2048
#define NH    16
#define NKV   2
#define HD    256
#define MAXS  4096
#define RD    64
#define GROUPS 8
#define ATT_SCALE 0.0625f
#define EPSV  1e-6f
#define NQKV  9216        // 8192 (q|gate) + 512 (k) + 512 (v)

typedef __nv_bfloat16 bf16;

// ---------------- scratch (static device globals; no allocs) ----------------
__device__ __align__(1024) float g_qkv  [(size_t)SEQ * NQKV];
__device__ __align__(1024) float g_scores[(size_t)NH * SEQ * SEQ];   // 256 MB
__device__ __align__(1024) float g_attn [(size_t)NH * SEQ * HD];

__device__ __align__(1024) bf16 g_hid_h[(size_t)SEQ * HID],      g_hid_l[(size_t)SEQ * HID];
__device__ __align__(1024) bf16 g_wqkv_h[(size_t)NQKV * HID],    g_wqkv_l[(size_t)NQKV * HID];
__device__ __align__(1024) bf16 g_ow_h [(size_t)HID * NH*HD],    g_ow_l [(size_t)HID * NH*HD];
__device__ __align__(1024) bf16 g_q_h  [(size_t)NH*SEQ*HD],      g_q_l  [(size_t)NH*SEQ*HD];
__device__ __align__(1024) bf16 g_k_h  [(size_t)NKV*SEQ*HD],     g_k_l  [(size_t)NKV*SEQ*HD];
__device__ __align__(1024) bf16 g_vT_h [(size_t)NKV*HD*SEQ],     g_vT_l [(size_t)NKV*HD*SEQ];
__device__ __align__(1024) bf16 g_gt_h [(size_t)SEQ * NH*HD],    g_gt_l [(size_t)SEQ * NH*HD];

// ---------------- PTX helpers (baseline PTX only) ----------------
__device__ __forceinline__ uint32_t smem_u32(const void* p) {
    uint32_t a;
    asm("{ .reg .u64 t; cvta.to.shared.u64 t, %1; cvt.u32.u64 %0, t; }" : "=r"(a) : "l"(p));
    return a;
}
#define CP_ASYNC16(dst, src) \
    asm volatile("cp.async.cg.shared.global [%0], [%1], 16;" :: "r"(dst), "l"(src) : "memory")
#define CP_COMMIT() asm volatile("cp.async.commit_group;" ::: "memory")
#define CP_WAIT(n)  asm volatile("cp.async.wait_group %0;" :: "n"(n) : "memory")

#define LDSM_X4(r0, r1, r2, r3, addr) \
    asm volatile("ldmatrix.sync.aligned.m8n8.x4.shared.b16 {%0,%1,%2,%3}, [%4];" \
        : "=r"(r0), "=r"(r1), "=r"(r2), "=r"(r3) : "r"(addr))

#define MMA16816(d, a, b0v, b1v) \
    asm volatile("mma.sync.aligned.m16n8k16.row.col.f32.bf16.bf16.f32 " \
        "{%0,%1,%2,%3}, {%4,%5,%6,%7}, {%8,%9}, {%0,%1,%2,%3};" \
        : "+f"((d)[0]), "+f"((d)[1]), "+f"((d)[2]), "+f"((d)[3]) \
        : "r"((a)[0]), "r"((a)[1]), "r"((a)[2]), "r"((a)[3]), "r"(b0v), "r"(b1v))

// ---------------- pack helpers ----------------
__device__ __forceinline__ uint32_t pack_hi2(float a, float b, float& la, float& lb) {
    bf16 ha = __float2bfloat16(a), hb = __float2bfloat16(b);
    la = a - __bfloat162float(ha);
    lb = b - __bfloat162float(hb);
    return (uint32_t)__bfloat16_as_ushort(ha) | ((uint32_t)__bfloat16_as_ushort(hb) << 16);
}
__device__ __forceinline__ uint32_t pack2(float a, float b) {
    return (uint32_t)__bfloat16_as_ushort(__float2bfloat16(a)) |
           ((uint32_t)__bfloat16_as_ushort(__float2bfloat16(b)) << 16);
}

// ---------------- split-bf16 HMMA GEMM (unchanged from R4) ----------------
#define GSMEM 131072

__global__ __launch_bounds__(512, 1)
void gemm_hmma(const bf16* __restrict__ Ah, const bf16* __restrict__ Al,
               const bf16* __restrict__ Bh, const bf16* __restrict__ Bl,
               float* __restrict__ C,
               int K, int lda, int ldb, int ldc,
               long long sA, long long sB, long long sC, int bDiv,
               float alpha, int mode)
{
    const int bx = blockIdx.x, by = blockIdx.y, bz = blockIdx.z;
    if (mode == 1 && bx > by) return;
    const int Keff = (mode == 2) ? min(K, (by + 1) * 128) : K;
    const int nch = Keff >> 6;

    extern __shared__ char smem[];
    const uint32_t sb = smem_u32(smem);

    const bf16* srcs[4] = { Ah + (size_t)bz * sA, Al + (size_t)bz * sA,
                            Bh + (size_t)(bz / bDiv) * sB, Bl + (size_t)(bz / bDiv) * sB };
    const int lds[4] = { lda, lda, ldb, ldb };
    const int rb [4] = { by * 128, by * 128, bx * 128, bx * 128 };

    const int tid = threadIdx.x, lane = tid & 31, wid = tid >> 5;
    const int wm = wid >> 2, wn = wid & 3;

    float acc[2][4][4];
    #pragma unroll
    for (int mt = 0; mt < 2; ++mt)
        #pragma unroll
        for (int nt = 0; nt < 4; ++nt)
            #pragma unroll
            for (int r = 0; r < 4; ++r) acc[mt][nt][r] = 0.f;

    auto issue = [&](int ch) {
        const uint32_t dbase = sb + (uint32_t)(ch & 1) * 65536u;
        const int kt = ch << 6;
        #pragma unroll
        for (int p = 0; p < 4; ++p) {
            #pragma unroll
            for (int i = 0; i < 2; ++i) {
                const int u = tid + i * 512;
                const int r = u >> 3, c = u & 7;
                const bf16* s = srcs[p] + (size_t)(rb[p] + r) * lds[p] + kt + c * 8;
                const uint32_t d = dbase + (uint32_t)(p * 16384 + r * 128 +
                                   ((c * 16) ^ ((r & 7) << 4)));
                CP_ASYNC16(d, (const void*)s);
            }
        }
        CP_COMMIT();
    };

    issue(0);
    for (int ch = 0; ch < nch; ++ch) {
        if (ch + 1 < nch) { issue(ch + 1); CP_WAIT(1); }
        else              { CP_WAIT(0); }
        __syncthreads();

        const uint32_t b0 = sb + (uint32_t)(ch & 1) * 65536u;

        #pragma unroll
        for (int ks = 0; ks < 4; ++ks) {
            uint32_t ah[2][4], alr[2][4], bh[2][4], blr[2][4];
            const uint32_t colk = (uint32_t)(ks * 32 + ((lane >> 4) << 4));
            #pragma unroll
            for (int mt = 0; mt < 2; ++mt) {
                const int row = wm * 32 + mt * 16 + (lane & 15);
                const uint32_t a0 = b0 + (uint32_t)(row * 128) + (colk ^ ((row & 7) << 4));
                LDSM_X4(ah [mt][0], ah [mt][1], ah [mt][2], ah [mt][3], a0);
                LDSM_X4(alr[mt][0], alr[mt][1], alr[mt][2], alr[mt][3], a0 + 16384u);
            }
            #pragma unroll
            for (int pr = 0; pr < 2; ++pr) {
                const int row = wn * 32 + pr * 16 + (lane & 15);
                const uint32_t a0 = b0 + 32768u + (uint32_t)(row * 128) + (colk ^ ((row & 7) << 4));
                LDSM_X4(bh [pr][0], bh [pr][1], bh [pr][2], bh [pr][3], a0);
                LDSM_X4(blr[pr][0], blr[pr][1], blr[pr][2], blr[pr][3], a0 + 16384u);
            }
            #pragma unroll
            for (int term = 0; term < 3; ++term) {
                #pragma unroll
                for (int mt = 0; mt < 2; ++mt) {
                    #pragma unroll
                    for (int nt = 0; nt < 4; ++nt) {
                        const uint32_t* af = (term == 2) ? alr[mt] : ah[mt];
                        const uint32_t b0v = (term == 1) ? blr[nt >> 1][nt & 1]
                                                         : bh [nt >> 1][nt & 1];
                        const uint32_t b1v = (term == 1) ? blr[nt >> 1][(nt & 1) + 2]
                                                         : bh [nt >> 1][(nt & 1) + 2];
                        MMA16816(acc[mt][nt], af, b0v, b1v);
                    }
                }
            }
        }
        __syncthreads();
    }

    float* pC = C + (size_t)bz * sC;
    #pragma unroll
    for (int mt = 0; mt < 2; ++mt) {
        #pragma unroll
        for (int nt = 0; nt < 4; ++nt) {
            const int row = by * 128 + wm * 32 + mt * 16 + (lane >> 2);
            const int col = bx * 128 + wn * 32 + nt * 8 + (lane & 3) * 2;
            float2 v0 = { acc[mt][nt][0] * alpha, acc[mt][nt][1] * alpha };
            float2 v1 = { acc[mt][nt][2] * alpha, acc[mt][nt][3] * alpha };
            *reinterpret_cast<float2*>(&pC[(size_t)row * ldc + col])       = v0;
            *reinterpret_cast<float2*>(&pC[(size_t)(row + 8) * ldc + col]) = v1;
        }
    }
}

// ---------------- fused online-softmax + PV kernel ----------------
// grid (16 qb [reversed], 16 h), 512 threads, 1 CTA/SM.
// smem: P (2 chunks x {hi,lo} x 16KB = 64KB) | V (2 chunks x {hi,lo} x 32KB = 128KB) | m/f/l
#define SPV_SMEM (65536 + 131072 + 2048)

__global__ __launch_bounds__(512, 1)
void spv_kernel(const float* __restrict__ S,
                const bf16* __restrict__ vTh, const bf16* __restrict__ vTl,
                float* __restrict__ Out)
{
    const int qb = (int)gridDim.x - 1 - (int)blockIdx.x;   // big blocks first
    const int h  = blockIdx.y;
    const int kv = h / GROUPS;

    extern __shared__ char smem[];
    const uint32_t sb = smem_u32(smem);
    const uint32_t P0 = sb;               // chunk c: +c*32768, lo +16384
    const uint32_t V0 = sb + 65536u;      // chunk c: +c*65536, lo +32768
    float* sm_m = reinterpret_cast<float*>(smem + 196608);
    float* sm_f = sm_m + 128;
    float* sm_l = sm_f + 128;

    const int tid = threadIdx.x, lane = tid & 31, wid = tid >> 5;
    const int wm = wid >> 2, wd = wid & 3;
    const int srow = tid >> 2, scg = tid & 3;

    float acc[2][8][4];
    #pragma unroll
    for (int a = 0; a < 2; ++a)
        #pragma unroll
        for (int b = 0; b < 8; ++b)
            #pragma unroll
            for (int c = 0; c < 4; ++c) acc[a][b][c] = 0.f;

    if (tid < 128) { sm_m[tid] = -1e30f; sm_l[tid] = 0.f; }

    const float* Sbase = S + ((size_t)h * SEQ + (size_t)qb * 128) * SEQ;
    const bf16* vh0 = vTh + (size_t)kv * HD * SEQ;
    const bf16* vl0 = vTl + (size_t)kv * HD * SEQ;

    for (int kb = 0; kb <= qb; ++kb) {
        __syncthreads();   // prev PV done; P/V regions free; sm_* visible

        // issue V tile (2 k-chunks x 2 planes, 256 d-rows x 128B each)
        #pragma unroll
        for (int c = 0; c < 2; ++c) {
            #pragma unroll
            for (int p = 0; p < 2; ++p) {
                const bf16* vs = p ? vl0 : vh0;
                #pragma unroll
                for (int i = 0; i < 4; ++i) {
                    const int u = tid + i * 512;        // 0..2047
                    const int r = u >> 3, un = u & 7;
                    const bf16* src = vs + (size_t)r * SEQ + kb * 128 + c * 64 + un * 8;
                    const uint32_t dst = V0 + (uint32_t)(c * 65536 + p * 32768 + r * 128 +
                                         ((un * 16) ^ ((r & 7) << 4)));
                    CP_ASYNC16(dst, (const void*)src);
                }
            }
        }
        CP_COMMIT();

        // online softmax over this 128x128 score block
        const float* sp = Sbase + (size_t)srow * SEQ + kb * 128 + scg * 32;
        const int gq = qb * 128 + srow;
        const int k0 = kb * 128 + scg * 32;
        float v[32];
        #pragma unroll
        for (int e8 = 0; e8 < 8; ++e8) {
            float4 t = *reinterpret_cast<const float4*>(sp + e8 * 4);
            v[e8*4+0]=t.x; v[e8*4+1]=t.y; v[e8*4+2]=t.z; v[e8*4+3]=t.w;
        }
        #pragma unroll
        for (int e = 0; e < 32; ++e)
            if (k0 + e > gq) v[e] = -1e30f;       // causal mask (garbage-safe overwrite)
        float pm = -1e30f;
        #pragma unroll
        for (int e = 0; e < 32; ++e) pm = fmaxf(pm, v[e]);
        pm = fmaxf(pm, __shfl_xor_sync(0xffffffffu, pm, 1));
        pm = fmaxf(pm, __shfl_xor_sync(0xffffffffu, pm, 2));
        const float m_old = sm_m[srow];
        const float m_new = fmaxf(m_old, pm);
        float psum = 0.f;
        #pragma unroll
        for (int e = 0; e < 32; ++e) {
            float p = __expf(v[e] - m_new);
            v[e] = p;
            psum += p;
        }
        psum += __shfl_xor_sync(0xffffffffu, psum, 1);
        psum += __shfl_xor_sync(0xffffffffu, psum, 2);
        if (scg == 0) {
            const float f = __expf(m_old - m_new);
            sm_m[srow] = m_new;
            sm_f[srow] = f;
            sm_l[srow] = sm_l[srow] * f + psum;
        }
        // write P (bf16 hi/lo) to swizzled smem
        {
            const int c = scg >> 1;
            const uint32_t base = P0 + (uint32_t)(c * 32768 + srow * 128);
            const int cb0 = (scg & 1) * 64;
            uint32_t hw[16], lw[16];
            #pragma unroll
            for (int e2 = 0; e2 < 16; ++e2) {
                float la, lb;
                hw[e2] = pack_hi2(v[e2*2], v[e2*2+1], la, lb);
                lw[e2] = pack2(la, lb);
            }
            #pragma unroll
            for (int u = 0; u < 4; ++u) {
                const uint32_t off = (uint32_t)((cb0 + u * 16) ^ ((srow & 7) << 4));
                asm volatile("st.shared.v4.b32 [%0], {%1,%2,%3,%4};"
                    :: "r"(base + off), "r"(hw[u*4]), "r"(hw[u*4+1]), "r"(hw[u*4+2]), "r"(hw[u*4+3]) : "memory");
                asm volatile("st.shared.v4.b32 [%0], {%1,%2,%3,%4};"
                    :: "r"(base + 16384u + off), "r"(lw[u*4]), "r"(lw[u*4+1]), "r"(lw[u*4+2]), "r"(lw[u*4+3]) : "memory");
            }
        }
        CP_WAIT(0);
        __syncthreads();

        // rescale O by exp(m_old - m_new)
        #pragma unroll
        for (int mt = 0; mt < 2; ++mt) {
            const int r0 = wm * 32 + mt * 16 + (lane >> 2);
            const float f0 = sm_f[r0], f1 = sm_f[r0 + 8];
            #pragma unroll
            for (int nn = 0; nn < 8; ++nn) {
                acc[mt][nn][0] *= f0; acc[mt][nn][1] *= f0;
                acc[mt][nn][2] *= f1; acc[mt][nn][3] *= f1;
            }
        }

        // PV: O[32q x 64d] += P[32q x 128k] * V^T[64d x 128k]^T  (3-term split)
        #pragma unroll
        for (int c = 0; c < 2; ++c) {
            const uint32_t pbase = P0 + (uint32_t)c * 32768u;
            const uint32_t vbase = V0 + (uint32_t)c * 65536u;
            #pragma unroll
            for (int ks = 0; ks < 4; ++ks) {
                const uint32_t colk = (uint32_t)(ks * 32 + ((lane >> 4) << 4));
                uint32_t ph_[2][4], pl_[2][4];
                #pragma unroll
                for (int mt = 0; mt < 2; ++mt) {
                    const int row = wm * 32 + mt * 16 + (lane & 15);
                    const uint32_t a0 = pbase + (uint32_t)(row * 128) + (colk ^ ((row & 7) << 4));
                    LDSM_X4(ph_[mt][0], ph_[mt][1], ph_[mt][2], ph_[mt][3], a0);
                    LDSM_X4(pl_[mt][0], pl_[mt][1], pl_[mt][2], pl_[mt][3], a0 + 16384u);
                }
                #pragma unroll
                for (int half = 0; half < 2; ++half) {
                    uint32_t bh_[2][4], bl_[2][4];
                    #pragma unroll
                    for (int pr = 0; pr < 2; ++pr) {
                        const int row = wd * 64 + (half * 2 + pr) * 16 + (lane & 15);
                        const uint32_t b0a = vbase + (uint32_t)(row * 128) + (colk ^ ((row & 7) << 4));
                        LDSM_X4(bh_[pr][0], bh_[pr][1], bh_[pr][2], bh_[pr][3], b0a);
                        LDSM_X4(bl_[pr][0], bl_[pr][1], bl_[pr][2], bl_[pr][3], b0a + 32768u);
                    }
                    #pragma unroll
                    for (int term = 0; term < 3; ++term) {
                        #pragma unroll
                        for (int mt = 0; mt < 2; ++mt) {
                            #pragma unroll
                            for (int n4 = 0; n4 < 4; ++n4) {
                                const int nn = half * 4 + n4;
                                const uint32_t* af = (term == 2) ? pl_[mt] : ph_[mt];
                                const uint32_t b0v = (term == 1) ? bl_[n4 >> 1][n4 & 1]
                                                                 : bh_[n4 >> 1][n4 & 1];
                                const uint32_t b1v = (term == 1) ? bl_[n4 >> 1][(n4 & 1) + 2]
                                                                 : bh_[n4 >> 1][(n4 & 1) + 2];
                                MMA16816(acc[mt][nn], af, b0v, b1v);
                            }
                        }
                    }
                }
            }
        }
    }

    __syncthreads();
    // normalize by 1/l and write out fp32 [h][q][d]
    #pragma unroll
    for (int mt = 0; mt < 2; ++mt) {
        const int r0 = wm * 32 + mt * 16 + (lane >> 2);
        const float il0 = 1.f / sm_l[r0];
        const float il1 = 1.f / sm_l[r0 + 8];
        const int row = qb * 128 + r0;
        #pragma unroll
        for (int nn = 0; nn < 8; ++nn) {
            const int col = wd * 64 + nn * 8 + (lane & 3) * 2;
            float2 v0 = { acc[mt][nn][0] * il0, acc[mt][nn][1] * il0 };
            float2 v1 = { acc[mt][nn][2] * il1, acc[mt][nn][3] * il1 };
            float* op = Out + ((size_t)h * SEQ + row) * HD + col;
            *reinterpret_cast<float2*>(op)            = v0;
            *reinterpret_cast<float2*>(op + 8 * HD)   = v1;
        }
    }
}

// ---------------- single fused fp32->(hi,lo) split over all 5 tensors ----------
// quads: hid [0,1048576) qw [.,5242880) kw [.,5505024) vw [.,5767168) ow [.,7864320)
__global__ void split_all_kernel(const float* __restrict__ hid, const float* __restrict__ qw,
                                 const float* __restrict__ kw, const float* __restrict__ vw,
                                 const float* __restrict__ ow,
                                 bf16* __restrict__ hidh, bf16* __restrict__ hidl,
                                 bf16* __restrict__ wh, bf16* __restrict__ wl,
                                 bf16* __restrict__ owh, bf16* __restrict__ owl)
{
    size_t i = (size_t)blockIdx.x * blockDim.x + threadIdx.x;
    if (i >= 7864320u) return;
    const float* src; bf16 *dh, *dl; size_t loc;
    if (i < 1048576u)      { src = hid; dh = hidh;            dl = hidl;            loc = i; }
    else if (i < 5242880u) { src = qw;  dh = wh;              dl = wl;              loc = i - 1048576u; }
    else if (i < 5505024u) { src = kw;  dh = wh + 16777216u;  dl = wl + 16777216u;  loc = i - 5242880u; }
    else if (i < 5767168u) { src = vw;  dh = wh + 17825792u;  dl = wl + 17825792u;  loc = i - 5505024u; }
    else                   { src = ow;  dh = owh;             dl = owl;             loc = i - 5767168u; }
    float4 v = reinterpret_cast<const float4*>(src)[loc];
    float lx, ly, lz, lw2;
    uint2 hh, ll;
    hh.x = pack_hi2(v.x, v.y, lx, ly);
    hh.y = pack_hi2(v.z, v.w, lz, lw2);
    ll.x = pack2(lx, ly); ll.y = pack2(lz, lw2);
    reinterpret_cast<uint2*>(dh)[loc] = hh;
    reinterpret_cast<uint2*>(dl)[loc] = ll;
}

// ---------------- block reduce ----------------
__device__ __forceinline__ float blk_reduce(float v, float* sred, int tid, int lane, int wid) {
    #pragma unroll
    for (int o = 16; o > 0; o >>= 1) v += __shfl_xor_sync(0xffffffffu, v, o);
    if (lane == 0) sred[wid] = v;
    __syncthreads();
    if (tid == 0) {
        float r = sred[0];
        #pragma unroll
        for (int w = 1; w < 8; ++w) r += sred[w];
        sred[8] = r;
    }
    __syncthreads();
    float r = sred[8];
    __syncthreads();
    return r;
}

// ---------------- RMSNorm + RoPE for Q -> split planes ----------------
__global__ __launch_bounds__(256)
void q_norm_rope_kernel(const float* __restrict__ qkv,
                        const float* __restrict__ cosb, const float* __restrict__ sinb,
                        const float* __restrict__ qw,
                        bf16* __restrict__ qh, bf16* __restrict__ ql)
{
    const int s = blockIdx.x, h = blockIdx.y, d = threadIdx.x;
    const int lane = d & 31, wid = d >> 5;
    float x = qkv[(size_t)s * NQKV + h * 512 + d];
    __shared__ float sred[9];
    __shared__ float xs[256];
    float r = blk_reduce(x * x, sred, d, lane, wid);
    r = rsqrtf(r * (1.f / HD) + EPSV);
    float xn = x * r * (1.f + qw[d]);
    xs[d] = xn;
    __syncthreads();
    float o = xn;
    if (d < RD) {
        float rot = (d < RD / 2) ? -xs[d + RD / 2] : xs[d - RD / 2];
        o = xn * cosb[(size_t)s * RD + d] + rot * sinb[(size_t)s * RD + d];
    }
    size_t idx = ((size_t)h * SEQ + s) * HD + d;
    bf16 hv = __float2bfloat16(o);
    qh[idx] = hv;
    ql[idx] = __float2bfloat16(o - __bfloat162float(hv));
}

// ---------------- RMSNorm + RoPE for K; caches + split planes ----------------
__global__ __launch_bounds__(256)
void kv_norm_rope_kernel(const float* __restrict__ qkv,
                         const float* __restrict__ cosb, const float* __restrict__ sinb,
                         const float* __restrict__ kw,
                         float* __restrict__ kcache, float* __restrict__ vcache,
                         bf16* __restrict__ kh, bf16* __restrict__ kl,
                         bf16* __restrict__ vTh, bf16* __restrict__ vTl)
{
    const int s = blockIdx.x, kv = blockIdx.y, d = threadIdx.x;
    const int lane = d & 31, wid = d >> 5;
    float x = qkv[(size_t)s * NQKV + 8192 + kv * 256 + d];
    float v = qkv[(size_t)s * NQKV + 8704 + kv * 256 + d];
    __shared__ float sred[9];
    __shared__ float xs[256];
    float r = blk_reduce(x * x, sred, d, lane, wid);
    r = rsqrtf(r * (1.f / HD) + EPSV);
    float xn = x * r * (1.f + kw[d]);
    xs[d] = xn;
    __syncthreads();
    float o = xn;
    if (d < RD) {
        float rot = (d < RD / 2) ? -xs[d + RD / 2] : xs[d - RD / 2];
        o = xn * cosb[(size_t)s * RD + d] + rot * sinb[(size_t)s * RD + d];
    }
    size_t cidx = ((size_t)kv * MAXS + s) * HD + d;
    kcache[cidx] = o;
    vcache[cidx] = v;
    size_t kidx = ((size_t)kv * SEQ + s) * HD + d;
    bf16 khv = __float2bfloat16(o);
    kh[kidx] = khv;
    kl[kidx] = __float2bfloat16(o - __bfloat162float(khv));
    size_t vidx = ((size_t)kv * HD + d) * SEQ + s;
    bf16 vhv = __float2bfloat16(v);
    vTh[vidx] = vhv;
    vTl[vidx] = __float2bfloat16(v - __bfloat162float(vhv));
}

// ---------------- zero pad caches rows SEQ..MAXS ----------------
__global__ void zero_pad_kernel(float* __restrict__ kcache, float* __restrict__ vcache)
{
    size_t idx = (size_t)blockIdx.x * blockDim.x + threadIdx.x;
    const size_t per_kv = (size_t)(MAXS - SEQ) * HD;
    if (idx >= (size_t)NKV * per_kv) return;
    size_t kv = idx / per_kv, rem = idx - kv * per_kv;
    size_t off = kv * (size_t)MAXS * HD + (size_t)SEQ * HD + rem;
    kcache[off] = 0.f;
    vcache[off] = 0.f;
}

// ---------------- gating (x4 vectorized) -> split planes ----------------
__global__ void gate_kernel(const float* __restrict__ attn, const float* __restrict__ qkv,
                            bf16* __restrict__ gh, bf16* __restrict__ gl)
{
    size_t idx = (size_t)blockIdx.x * blockDim.x + threadIdx.x;
    if (idx >= (size_t)SEQ * NH * HD / 4) return;
    int s = (int)(idx >> 10);
    int r = (int)(idx & 1023);
    int h = r >> 6, dq = (r & 63) * 4;
    float4 a = *reinterpret_cast<const float4*>(&attn[((size_t)h * SEQ + s) * HD + dq]);
    float4 g = *reinterpret_cast<const float4*>(&qkv[(size_t)s * NQKV + h * 512 + 256 + dq]);
    float o0 = a.x * (1.f / (1.f + __expf(-g.x)));
    float o1 = a.y * (1.f / (1.f + __expf(-g.y)));
    float o2 = a.z * (1.f / (1.f + __expf(-g.z)));
    float o3 = a.w * (1.f / (1.f + __expf(-g.w)));
    float l0, l1, l2, l3;
    uint2 hh = { pack_hi2(o0, o1, l0, l1), pack_hi2(o2, o3, l2, l3) };
    uint2 ll = { pack2(l0, l1), pack2(l2, l3) };
    size_t o = (size_t)s * (NH * HD) + h * HD + dq;
    *reinterpret_cast<uint2*>(gh + o) = hh;
    *reinterpret_cast<uint2*>(gl + o) = ll;
}

// ---------------- launch ----------------
extern "C" void kernel_launch(void* const* d_in, const int* in_sizes, int n_in,
                              void* d_out, int out_size)
{
    const float* hidden = (const float*)d_in[0];
    const float* cosb   = (const float*)d_in[1];
    const float* sinb   = (const float*)d_in[2];
    const float* q_w    = (const float*)d_in[3];
    const float* k_w    = (const float*)d_in[4];
    const float* v_w    = (const float*)d_in[5];
    const float* o_w    = (const float*)d_in[6];
    const float* qnw    = (const float*)d_in[7];
    const float* knw    = (const float*)d_in[8];

    float* hidden_out = (float*)d_out;
    float* kcache = hidden_out + (size_t)SEQ * HID;
    float* vcache = kcache + (size_t)NKV * MAXS * HD;

    float *qkv, *sc, *at;
    bf16 *hidh, *hidl, *wh, *wl, *owh, *owl;
    bf16 *qh, *ql, *kh, *kl, *vTh, *vTl, *gth, *gtl;
    cudaGetSymbolAddress((void**)&qkv, g_qkv);
    cudaGetSymbolAddress((void**)&sc, g_scores);
    cudaGetSymbolAddress((void**)&at, g_attn);
    cudaGetSymbolAddress((void**)&hidh, g_hid_h); cudaGetSymbolAddress((void**)&hidl, g_hid_l);
    cudaGetSymbolAddress((void**)&wh, g_wqkv_h);  cudaGetSymbolAddress((void**)&wl, g_wqkv_l);
    cudaGetSymbolAddress((void**)&owh, g_ow_h);   cudaGetSymbolAddress((void**)&owl, g_ow_l);
    cudaGetSymbolAddress((void**)&qh, g_q_h);     cudaGetSymbolAddress((void**)&ql, g_q_l);
    cudaGetSymbolAddress((void**)&kh, g_k_h);     cudaGetSymbolAddress((void**)&kl, g_k_l);
    cudaGetSymbolAddress((void**)&vTh, g_vT_h);   cudaGetSymbolAddress((void**)&vTl, g_vT_l);
    cudaGetSymbolAddress((void**)&gth, g_gt_h);   cudaGetSymbolAddress((void**)&gtl, g_gt_l);

    cudaFuncSetAttribute(gemm_hmma, cudaFuncAttributeMaxDynamicSharedMemorySize, GSMEM);
    cudaFuncSetAttribute(spv_kernel, cudaFuncAttributeMaxDynamicSharedMemorySize, SPV_SMEM);

    dim3 blk(256);
    dim3 gblk(512);

    // 1) all fp32->bf16 splits in one launch
    split_all_kernel<<<30720, blk>>>(hidden, q_w, k_w, v_w, o_w,
                                     hidh, hidl, wh, wl, owh, owl);

    // 2) fused qkv projection [2048 x 9216]
    gemm_hmma<<<dim3(NQKV/128, SEQ/128, 1), gblk, GSMEM>>>(
        hidh, hidl, wh, wl, qkv, HID, HID, HID, NQKV, 0, 0, 0, 1, 1.f, 0);

    // 3-5) norms + rope + caches + pad
    q_norm_rope_kernel<<<dim3(SEQ, NH), blk>>>(qkv, cosb, sinb, qnw, qh, ql);
    kv_norm_rope_kernel<<<dim3(SEQ, NKV), blk>>>(qkv, cosb, sinb, knw,
                                                 kcache, vcache, kh, kl, vTh, vTl);
    zero_pad_kernel<<<(unsigned)(((size_t)NKV * (MAXS - SEQ) * HD + 255) / 256), blk>>>(kcache, vcache);

    // 6) scores = Q @ K^T * scale (causal block skip)
    gemm_hmma<<<dim3(SEQ/128, SEQ/128, NH), gblk, GSMEM>>>(
        qh, ql, kh, kl, sc, HD, HD, HD, SEQ,
        (long long)SEQ * HD, (long long)SEQ * HD, (long long)SEQ * SEQ, GROUPS,
        ATT_SCALE, 1);

    // 7) fused online softmax + PV
    spv_kernel<<<dim3(SEQ/128, NH), gblk, SPV_SMEM>>>(sc, vTh, vTl, at);

    // 8) gating
    gate_kernel<<<(unsigned)(((size_t)SEQ * NH * HD / 4 + 255) / 256), blk>>>(at, qkv, gth, gtl);

    // 9) hidden_out = gated @ o_w^T
    gemm_hmma<<<dim3(HID/128, SEQ/128, 1), gblk, GSMEM>>>(
        gth, gtl, owh, owl, hidden_out, NH*HD, NH*HD, NH*HD, HID, 0, 0, 0, 1, 1.f, 0);
}

// round 6
// speedup vs baseline: 1.1247x; 1.1247x over previous
#include <cuda_runtime.h>
#include <cuda_bf16.h>
#include <cuda_fp16.h>
#include <cstdint>
#include <math.h>

// ---------------- problem constants ----------------
#define SEQ   2048
#define HID   2048
#define NH    16
#define NKV   2
#define HD    256
#define MAXS  4096
#define RD    64
#define GROUPS 8
#define ATT_SCALE 0.0625f
#define EPSV  1e-6f
#define NQKV  9216

typedef __nv_bfloat16 bf16;

// ---------------- scratch ----------------
__device__ __align__(1024) float g_qkv  [(size_t)SEQ * NQKV];
__device__ __align__(1024) float g_scores[(size_t)NH * SEQ * SEQ];
__device__ __align__(1024) float g_attn [(size_t)NH * SEQ * HD];

__device__ __align__(1024) bf16 g_hid_h[(size_t)SEQ * HID],      g_hid_l[(size_t)SEQ * HID];
__device__ __align__(1024) bf16 g_wqkv_h[(size_t)NQKV * HID],    g_wqkv_l[(size_t)NQKV * HID];
__device__ __align__(1024) __half g_ow_h[(size_t)HID * NH*HD];
__device__ __align__(1024) bf16 g_q_h  [(size_t)NH*SEQ*HD],      g_q_l  [(size_t)NH*SEQ*HD];
__device__ __align__(1024) bf16 g_k_h  [(size_t)NKV*SEQ*HD],     g_k_l  [(size_t)NKV*SEQ*HD];
__device__ __align__(1024) bf16 g_vT_h [(size_t)NKV*HD*SEQ],     g_vT_l [(size_t)NKV*HD*SEQ];
__device__ __align__(1024) bf16 g_p_h  [(size_t)NH*SEQ*SEQ],     g_p_l  [(size_t)NH*SEQ*SEQ];
__device__ __align__(1024) __half g_gt_h[(size_t)SEQ * NH*HD],   g_gt_l[(size_t)SEQ * NH*HD];

// ---------------- PTX helpers ----------------
__device__ __forceinline__ uint32_t smem_u32(const void* p) {
    uint32_t a;
    asm("{ .reg .u64 t; cvta.to.shared.u64 t, %1; cvt.u32.u64 %0, t; }" : "=r"(a) : "l"(p));
    return a;
}
#define CP_ASYNC16(dst, src) \
    asm volatile("cp.async.cg.shared.global [%0], [%1], 16;" :: "r"(dst), "l"(src) : "memory")
#define CP_COMMIT() asm volatile("cp.async.commit_group;" ::: "memory")
#define CP_WAIT(n)  asm volatile("cp.async.wait_group %0;" :: "n"(n) : "memory")

#define LDSM_X4(r0, r1, r2, r3, addr) \
    asm volatile("ldmatrix.sync.aligned.m8n8.x4.shared.b16 {%0,%1,%2,%3}, [%4];" \
        : "=r"(r0), "=r"(r1), "=r"(r2), "=r"(r3) : "r"(addr))

#define MMA_BF16(d, a, b0v, b1v) \
    asm volatile("mma.sync.aligned.m16n8k16.row.col.f32.bf16.bf16.f32 " \
        "{%0,%1,%2,%3}, {%4,%5,%6,%7}, {%8,%9}, {%0,%1,%2,%3};" \
        : "+f"((d)[0]), "+f"((d)[1]), "+f"((d)[2]), "+f"((d)[3]) \
        : "r"((a)[0]), "r"((a)[1]), "r"((a)[2]), "r"((a)[3]), "r"(b0v), "r"(b1v))

#define MMA_F16(d, a, b0v, b1v) \
    asm volatile("mma.sync.aligned.m16n8k16.row.col.f32.f16.f16.f32 " \
        "{%0,%1,%2,%3}, {%4,%5,%6,%7}, {%8,%9}, {%0,%1,%2,%3};" \
        : "+f"((d)[0]), "+f"((d)[1]), "+f"((d)[2]), "+f"((d)[3]) \
        : "r"((a)[0]), "r"((a)[1]), "r"((a)[2]), "r"((a)[3]), "r"(b0v), "r"(b1v))

// ---------------- pack helpers ----------------
__device__ __forceinline__ uint32_t pack_hi2(float a, float b, float& la, float& lb) {
    bf16 ha = __float2bfloat16(a), hb = __float2bfloat16(b);
    la = a - __bfloat162float(ha);
    lb = b - __bfloat162float(hb);
    return (uint32_t)__bfloat16_as_ushort(ha) | ((uint32_t)__bfloat16_as_ushort(hb) << 16);
}
__device__ __forceinline__ uint32_t pack2(float a, float b) {
    return (uint32_t)__bfloat16_as_ushort(__float2bfloat16(a)) |
           ((uint32_t)__bfloat16_as_ushort(__float2bfloat16(b)) << 16);
}
__device__ __forceinline__ uint32_t packh2(float a, float b) {
    __half2 h = __floats2half2_rn(a, b);
    return *reinterpret_cast<uint32_t*>(&h);
}
__device__ __forceinline__ uint32_t packh_hi2(float a, float b, float& la, float& lb) {
    __half ha = __float2half_rn(a), hb = __float2half_rn(b);
    la = a - __half2float(ha);
    lb = b - __half2float(hb);
    __half2 h2 = __halves2half2(ha, hb);
    return *reinterpret_cast<uint32_t*>(&h2);
}

// ---------------- split-precision HMMA GEMM, 3-stage pipeline ----------------
// F16_2T=false: bf16 3-term (AhBh+AhBl+AlBh), 4 planes/chunk, 192KB smem.
// F16_2T=true : fp16 2-term (AhBh+AlBh), B single plane, 3 planes/chunk, 144KB.
// mode 0 plain; 1 causal block-skip; 2 causal K-limit.
template<bool F16_2T>
__global__ __launch_bounds__(512, 1)
void gemm_hmma(const uint16_t* __restrict__ Ah, const uint16_t* __restrict__ Al,
               const uint16_t* __restrict__ Bh, const uint16_t* __restrict__ Bl,
               float* __restrict__ C,
               int K, int lda, int ldb, int ldc,
               long long sA, long long sB, long long sC, int bDiv,
               float alpha, int mode)
{
    constexpr int NPLANES = F16_2T ? 3 : 4;
    constexpr uint32_t STG = NPLANES * 16384u;

    const int bx = blockIdx.x, by = blockIdx.y, bz = blockIdx.z;
    if (mode == 1 && bx > by) return;
    const int Keff = (mode == 2) ? min(K, (by + 1) * 128) : K;
    const int nch = Keff >> 6;

    extern __shared__ char smem[];
    const uint32_t sb = smem_u32(smem);

    const uint16_t* srcs[4] = { Ah + (size_t)bz * sA, Al + (size_t)bz * sA,
                                Bh + (size_t)(bz / bDiv) * sB,
                                F16_2T ? nullptr : Bl + (size_t)(bz / bDiv) * sB };
    const int lds[4] = { lda, lda, ldb, ldb };
    const int rb [4] = { by * 128, by * 128, bx * 128, bx * 128 };

    const int tid = threadIdx.x, lane = tid & 31, wid = tid >> 5;
    const int wm = wid >> 2, wn = wid & 3;

    float acc[2][4][4];
    #pragma unroll
    for (int mt = 0; mt < 2; ++mt)
        #pragma unroll
        for (int nt = 0; nt < 4; ++nt)
            #pragma unroll
            for (int r = 0; r < 4; ++r) acc[mt][nt][r] = 0.f;

    auto issue = [&](int ch) {
        const uint32_t dbase = sb + (uint32_t)(ch % 3) * STG;
        const int kt = ch << 6;
        #pragma unroll
        for (int p = 0; p < NPLANES; ++p) {
            #pragma unroll
            for (int i = 0; i < 2; ++i) {
                const int u = tid + i * 512;
                const int r = u >> 3, c = u & 7;
                const uint16_t* s = srcs[p] + (size_t)(rb[p] + r) * lds[p] + kt + c * 8;
                const uint32_t d = dbase + (uint32_t)(p * 16384 + r * 128 +
                                   ((c * 16) ^ ((r & 7) << 4)));
                CP_ASYNC16(d, (const void*)s);
            }
        }
        CP_COMMIT();
    };

    issue(0);
    issue(1);
    for (int ch = 0; ch < nch; ++ch) {
        if (ch + 1 < nch) { CP_WAIT(1); }
        else              { CP_WAIT(0); }
        __syncthreads();
        if (ch + 2 < nch) issue(ch + 2);

        const uint32_t b0 = sb + (uint32_t)(ch % 3) * STG;

        #pragma unroll
        for (int ks = 0; ks < 4; ++ks) {
            const uint32_t colk = (uint32_t)(ks * 32 + ((lane >> 4) << 4));
            uint32_t ah[2][4], alr[2][4], bh[2][4], blr[2][4];
            #pragma unroll
            for (int mt = 0; mt < 2; ++mt) {
                const int row = wm * 32 + mt * 16 + (lane & 15);
                const uint32_t a0 = b0 + (uint32_t)(row * 128) + (colk ^ ((row & 7) << 4));
                LDSM_X4(ah [mt][0], ah [mt][1], ah [mt][2], ah [mt][3], a0);
                LDSM_X4(alr[mt][0], alr[mt][1], alr[mt][2], alr[mt][3], a0 + 16384u);
            }
            #pragma unroll
            for (int pr = 0; pr < 2; ++pr) {
                const int row = wn * 32 + pr * 16 + (lane & 15);
                const uint32_t a0 = b0 + 32768u + (uint32_t)(row * 128) + (colk ^ ((row & 7) << 4));
                LDSM_X4(bh[pr][0], bh[pr][1], bh[pr][2], bh[pr][3], a0);
                if (!F16_2T)
                    LDSM_X4(blr[pr][0], blr[pr][1], blr[pr][2], blr[pr][3], a0 + 16384u);
            }
            if (F16_2T) {
                #pragma unroll
                for (int term = 0; term < 2; ++term) {
                    #pragma unroll
                    for (int mt = 0; mt < 2; ++mt) {
                        #pragma unroll
                        for (int nt = 0; nt < 4; ++nt) {
                            const uint32_t* af = (term == 1) ? alr[mt] : ah[mt];
                            const uint32_t b0v = bh[nt >> 1][nt & 1];
                            const uint32_t b1v = bh[nt >> 1][(nt & 1) + 2];
                            MMA_F16(acc[mt][nt], af, b0v, b1v);
                        }
                    }
                }
            } else {
                #pragma unroll
                for (int term = 0; term < 3; ++term) {
                    #pragma unroll
                    for (int mt = 0; mt < 2; ++mt) {
                        #pragma unroll
                        for (int nt = 0; nt < 4; ++nt) {
                            const uint32_t* af = (term == 2) ? alr[mt] : ah[mt];
                            const uint32_t b0v = (term == 1) ? blr[nt >> 1][nt & 1]
                                                             : bh [nt >> 1][nt & 1];
                            const uint32_t b1v = (term == 1) ? blr[nt >> 1][(nt & 1) + 2]
                                                             : bh [nt >> 1][(nt & 1) + 2];
                            MMA_BF16(acc[mt][nt], af, b0v, b1v);
                        }
                    }
                }
            }
        }
    }

    float* pC = C + (size_t)bz * sC;
    #pragma unroll
    for (int mt = 0; mt < 2; ++mt) {
        #pragma unroll
        for (int nt = 0; nt < 4; ++nt) {
            const int row = by * 128 + wm * 32 + mt * 16 + (lane >> 2);
            const int col = bx * 128 + wn * 32 + nt * 8 + (lane & 3) * 2;
            float2 v0 = { acc[mt][nt][0] * alpha, acc[mt][nt][1] * alpha };
            float2 v1 = { acc[mt][nt][2] * alpha, acc[mt][nt][3] * alpha };
            *reinterpret_cast<float2*>(&pC[(size_t)row * ldc + col])       = v0;
            *reinterpret_cast<float2*>(&pC[(size_t)(row + 8) * ldc + col]) = v1;
        }
    }
}

// ---------------- weight splits: q/k/v -> bf16 hi/lo (concat), o_w -> fp16 ----
__global__ void split_w_kernel(const float* __restrict__ qw, const float* __restrict__ kw,
                               const float* __restrict__ vw, const float* __restrict__ ow,
                               bf16* __restrict__ wh, bf16* __restrict__ wl,
                               __half* __restrict__ owh)
{
    size_t i = (size_t)blockIdx.x * blockDim.x + threadIdx.x;
    if (i >= 6815744u) return;
    if (i < 4718592u) {   // bf16 hi/lo planes
        const float* src; size_t loc; bf16 *dh, *dl;
        if (i < 4194304u)      { src = qw; loc = i;            dh = wh;              dl = wl; }
        else if (i < 4456448u) { src = kw; loc = i - 4194304u; dh = wh + 16777216u;  dl = wl + 16777216u; }
        else                   { src = vw; loc = i - 4456448u; dh = wh + 17825792u;  dl = wl + 17825792u; }
        float4 v = reinterpret_cast<const float4*>(src)[loc];
        float lx, ly, lz, lw2;
        uint2 hh, ll;
        hh.x = pack_hi2(v.x, v.y, lx, ly);
        hh.y = pack_hi2(v.z, v.w, lz, lw2);
        ll.x = pack2(lx, ly); ll.y = pack2(lz, lw2);
        reinterpret_cast<uint2*>(dh)[loc] = hh;
        reinterpret_cast<uint2*>(dl)[loc] = ll;
    } else {              // o_w -> single fp16 plane
        size_t loc = i - 4718592u;
        float4 v = reinterpret_cast<const float4*>(ow)[loc];
        uint2 hh = { packh2(v.x, v.y), packh2(v.z, v.w) };
        reinterpret_cast<uint2*>(owh)[loc] = hh;
    }
}

// ---------------- activation split: hidden -> bf16 hi/lo ----------------
__global__ void split_a_kernel(const float* __restrict__ x,
                               bf16* __restrict__ hi, bf16* __restrict__ lo)
{
    size_t i = (size_t)blockIdx.x * blockDim.x + threadIdx.x;
    if (i >= 1048576u) return;
    float4 v = reinterpret_cast<const float4*>(x)[i];
    float lx, ly, lz, lw2;
    uint2 hh, ll;
    hh.x = pack_hi2(v.x, v.y, lx, ly);
    hh.y = pack_hi2(v.z, v.w, lz, lw2);
    ll.x = pack2(lx, ly); ll.y = pack2(lz, lw2);
    reinterpret_cast<uint2*>(hi)[i] = hh;
    reinterpret_cast<uint2*>(lo)[i] = ll;
}

// ---------------- block reduce ----------------
__device__ __forceinline__ float blk_reduce(float v, bool do_max, float* sred,
                                            int tid, int lane, int wid) {
    #pragma unroll
    for (int o = 16; o > 0; o >>= 1) {
        float t = __shfl_xor_sync(0xffffffffu, v, o);
        v = do_max ? fmaxf(v, t) : (v + t);
    }
    if (lane == 0) sred[wid] = v;
    __syncthreads();
    if (tid == 0) {
        float r = sred[0];
        #pragma unroll
        for (int w = 1; w < 8; ++w) r = do_max ? fmaxf(r, sred[w]) : (r + sred[w]);
        sred[8] = r;
    }
    __syncthreads();
    float r = sred[8];
    __syncthreads();
    return r;
}

// ---------------- RMSNorm + RoPE for Q ----------------
__global__ __launch_bounds__(256)
void q_norm_rope_kernel(const float* __restrict__ qkv,
                        const float* __restrict__ cosb, const float* __restrict__ sinb,
                        const float* __restrict__ qw,
                        bf16* __restrict__ qh, bf16* __restrict__ ql)
{
    const int s = blockIdx.x, h = blockIdx.y, d = threadIdx.x;
    const int lane = d & 31, wid = d >> 5;
    float x = qkv[(size_t)s * NQKV + h * 512 + d];
    __shared__ float sred[9];
    __shared__ float xs[256];
    float r = blk_reduce(x * x, false, sred, d, lane, wid);
    r = rsqrtf(r * (1.f / HD) + EPSV);
    float xn = x * r * (1.f + qw[d]);
    xs[d] = xn;
    __syncthreads();
    float o = xn;
    if (d < RD) {
        float rot = (d < RD / 2) ? -xs[d + RD / 2] : xs[d - RD / 2];
        o = xn * cosb[(size_t)s * RD + d] + rot * sinb[(size_t)s * RD + d];
    }
    size_t idx = ((size_t)h * SEQ + s) * HD + d;
    bf16 hv = __float2bfloat16(o);
    qh[idx] = hv;
    ql[idx] = __float2bfloat16(o - __bfloat162float(hv));
}

// ---------------- RMSNorm + RoPE for K; caches + planes ----------------
__global__ __launch_bounds__(256)
void kv_norm_rope_kernel(const float* __restrict__ qkv,
                         const float* __restrict__ cosb, const float* __restrict__ sinb,
                         const float* __restrict__ kw,
                         float* __restrict__ kcache, float* __restrict__ vcache,
                         bf16* __restrict__ kh, bf16* __restrict__ kl,
                         bf16* __restrict__ vTh, bf16* __restrict__ vTl)
{
    const int s = blockIdx.x, kv = blockIdx.y, d = threadIdx.x;
    const int lane = d & 31, wid = d >> 5;
    float x = qkv[(size_t)s * NQKV + 8192 + kv * 256 + d];
    float v = qkv[(size_t)s * NQKV + 8704 + kv * 256 + d];
    __shared__ float sred[9];
    __shared__ float xs[256];
    float r = blk_reduce(x * x, false, sred, d, lane, wid);
    r = rsqrtf(r * (1.f / HD) + EPSV);
    float xn = x * r * (1.f + kw[d]);
    xs[d] = xn;
    __syncthreads();
    float o = xn;
    if (d < RD) {
        float rot = (d < RD / 2) ? -xs[d + RD / 2] : xs[d - RD / 2];
        o = xn * cosb[(size_t)s * RD + d] + rot * sinb[(size_t)s * RD + d];
    }
    size_t cidx = ((size_t)kv * MAXS + s) * HD + d;
    kcache[cidx] = o;
    vcache[cidx] = v;
    size_t kidx = ((size_t)kv * SEQ + s) * HD + d;
    bf16 khv = __float2bfloat16(o);
    kh[kidx] = khv;
    kl[kidx] = __float2bfloat16(o - __bfloat162float(khv));
    size_t vidx = ((size_t)kv * HD + d) * SEQ + s;
    bf16 vhv = __float2bfloat16(v);
    vTh[vidx] = vhv;
    vTl[vidx] = __float2bfloat16(v - __bfloat162float(vhv));
}

// ---------------- zero pad caches rows SEQ..MAXS ----------------
__global__ void zero_pad_kernel(float* __restrict__ kcache, float* __restrict__ vcache)
{
    size_t idx = (size_t)blockIdx.x * blockDim.x + threadIdx.x;
    const size_t per_kv = (size_t)(MAXS - SEQ) * HD;
    if (idx >= (size_t)NKV * per_kv) return;
    size_t kv = idx / per_kv, rem = idx - kv * per_kv;
    size_t off = kv * (size_t)MAXS * HD + (size_t)SEQ * HD + rem;
    kcache[off] = 0.f;
    vcache[off] = 0.f;
}

// ---------------- causal softmax (register row) -> bf16 P planes ----------------
__global__ __launch_bounds__(256)
void softmax_kernel(const float* __restrict__ scores,
                    bf16* __restrict__ ph, bf16* __restrict__ pl)
{
    const int i = blockIdx.x, h = blockIdx.y, tid = threadIdx.x;
    const int lane = tid & 31, wid = tid >> 5;
    const float* row = scores + ((size_t)h * SEQ + i) * SEQ;
    bf16* prh = ph + ((size_t)h * SEQ + i) * SEQ;
    bf16* prl = pl + ((size_t)h * SEQ + i) * SEQ;
    const int n = i + 1;
    const int end = ((i >> 7) + 1) << 7;
    const int j0 = tid * 8;
    __shared__ float sred[9];

    float v[8];
    if (j0 < end) {
        float4 a = *reinterpret_cast<const float4*>(row + j0);
        float4 b = *reinterpret_cast<const float4*>(row + j0 + 4);
        v[0]=a.x; v[1]=a.y; v[2]=a.z; v[3]=a.w;
        v[4]=b.x; v[5]=b.y; v[6]=b.z; v[7]=b.w;
    } else {
        #pragma unroll
        for (int e = 0; e < 8; ++e) v[e] = -1e30f;
    }

    float m = -1e30f;
    #pragma unroll
    for (int e = 0; e < 8; ++e) if (j0 + e < n) m = fmaxf(m, v[e]);
    m = blk_reduce(m, true, sred, tid, lane, wid);

    float sum = 0.f;
    #pragma unroll
    for (int e = 0; e < 8; ++e) {
        float p = (j0 + e < n) ? __expf(v[e] - m) : 0.f;
        v[e] = p;
        sum += p;
    }
    sum = blk_reduce(sum, false, sred, tid, lane, wid);
    const float inv = 1.f / sum;

    if (j0 < end) {
        uint4 hh, ll;
        float lo[8];
        float p0 = v[0]*inv, p1 = v[1]*inv, p2 = v[2]*inv, p3 = v[3]*inv;
        float p4 = v[4]*inv, p5 = v[5]*inv, p6 = v[6]*inv, p7 = v[7]*inv;
        hh.x = pack_hi2(p0, p1, lo[0], lo[1]);
        hh.y = pack_hi2(p2, p3, lo[2], lo[3]);
        hh.z = pack_hi2(p4, p5, lo[4], lo[5]);
        hh.w = pack_hi2(p6, p7, lo[6], lo[7]);
        ll.x = pack2(lo[0], lo[1]); ll.y = pack2(lo[2], lo[3]);
        ll.z = pack2(lo[4], lo[5]); ll.w = pack2(lo[6], lo[7]);
        *reinterpret_cast<uint4*>(prh + j0) = hh;
        *reinterpret_cast<uint4*>(prl + j0) = ll;
    }
}

// ---------------- gating -> fp16 hi/lo planes ----------------
__global__ void gate_kernel(const float* __restrict__ attn, const float* __restrict__ qkv,
                            __half* __restrict__ gh, __half* __restrict__ gl)
{
    size_t idx = (size_t)blockIdx.x * blockDim.x + threadIdx.x;
    if (idx >= (size_t)SEQ * NH * HD / 4) return;
    int s = (int)(idx >> 10);
    int r = (int)(idx & 1023);
    int h = r >> 6, dq = (r & 63) * 4;
    float4 a = *reinterpret_cast<const float4*>(&attn[((size_t)h * SEQ + s) * HD + dq]);
    float4 g = *reinterpret_cast<const float4*>(&qkv[(size_t)s * NQKV + h * 512 + 256 + dq]);
    float o0 = a.x * (1.f / (1.f + __expf(-g.x)));
    float o1 = a.y * (1.f / (1.f + __expf(-g.y)));
    float o2 = a.z * (1.f / (1.f + __expf(-g.z)));
    float o3 = a.w * (1.f / (1.f + __expf(-g.w)));
    float l0, l1, l2, l3;
    uint2 hh = { packh_hi2(o0, o1, l0, l1), packh_hi2(o2, o3, l2, l3) };
    uint2 ll = { packh2(l0, l1), packh2(l2, l3) };
    size_t o = (size_t)s * (NH * HD) + h * HD + dq;
    *reinterpret_cast<uint2*>(gh + o) = hh;
    *reinterpret_cast<uint2*>(gl + o) = ll;
}

// ---------------- launch ----------------
extern "C" void kernel_launch(void* const* d_in, const int* in_sizes, int n_in,
                              void* d_out, int out_size)
{
    const float* hidden = (const float*)d_in[0];
    const float* cosb   = (const float*)d_in[1];
    const float* sinb   = (const float*)d_in[2];
    const float* q_w    = (const float*)d_in[3];
    const float* k_w    = (const float*)d_in[4];
    const float* v_w    = (const float*)d_in[5];
    const float* o_w    = (const float*)d_in[6];
    const float* qnw    = (const float*)d_in[7];
    const float* knw    = (const float*)d_in[8];

    float* hidden_out = (float*)d_out;
    float* kcache = hidden_out + (size_t)SEQ * HID;
    float* vcache = kcache + (size_t)NKV * MAXS * HD;

    float *qkv, *sc, *at;
    bf16 *hidh, *hidl, *wh, *wl;
    __half *owh, *gth, *gtl;
    bf16 *qh, *ql, *kh, *kl, *vTh, *vTl, *ph, *pl;
    cudaGetSymbolAddress((void**)&qkv, g_qkv);
    cudaGetSymbolAddress((void**)&sc, g_scores);
    cudaGetSymbolAddress((void**)&at, g_attn);
    cudaGetSymbolAddress((void**)&hidh, g_hid_h); cudaGetSymbolAddress((void**)&hidl, g_hid_l);
    cudaGetSymbolAddress((void**)&wh, g_wqkv_h);  cudaGetSymbolAddress((void**)&wl, g_wqkv_l);
    cudaGetSymbolAddress((void**)&owh, g_ow_h);
    cudaGetSymbolAddress((void**)&qh, g_q_h);     cudaGetSymbolAddress((void**)&ql, g_q_l);
    cudaGetSymbolAddress((void**)&kh, g_k_h);     cudaGetSymbolAddress((void**)&kl, g_k_l);
    cudaGetSymbolAddress((void**)&vTh, g_vT_h);   cudaGetSymbolAddress((void**)&vTl, g_vT_l);
    cudaGetSymbolAddress((void**)&ph, g_p_h);     cudaGetSymbolAddress((void**)&pl, g_p_l);
    cudaGetSymbolAddress((void**)&gth, g_gt_h);   cudaGetSymbolAddress((void**)&gtl, g_gt_l);

    cudaFuncSetAttribute(gemm_hmma<false>, cudaFuncAttributeMaxDynamicSharedMemorySize, 196608);
    cudaFuncSetAttribute(gemm_hmma<true>,  cudaFuncAttributeMaxDynamicSharedMemorySize, 147456);

    dim3 blk(256);
    dim3 gblk(512);

    // 1) cache zero-pad (independent)
    zero_pad_kernel<<<(unsigned)(((size_t)NKV * (MAXS - SEQ) * HD + 255) / 256), blk>>>(kcache, vcache);
    // 2) weight splits
    split_w_kernel<<<26624, blk>>>(q_w, k_w, v_w, o_w, wh, wl, owh);
    // 3) activation split
    split_a_kernel<<<4096, blk>>>(hidden, hidh, hidl);

    // 4) fused qkv projection [2048 x 9216]  (target of ncu capture)
    gemm_hmma<false><<<dim3(NQKV/128, SEQ/128, 1), gblk, 196608>>>(
        (const uint16_t*)hidh, (const uint16_t*)hidl, (const uint16_t*)wh, (const uint16_t*)wl,
        qkv, HID, HID, HID, NQKV, 0, 0, 0, 1, 1.f, 0);

    // 5-6) norms + rope + caches
    q_norm_rope_kernel<<<dim3(SEQ, NH), blk>>>(qkv, cosb, sinb, qnw, qh, ql);
    kv_norm_rope_kernel<<<dim3(SEQ, NKV), blk>>>(qkv, cosb, sinb, knw,
                                                 kcache, vcache, kh, kl, vTh, vTl);

    // 7) scores = Q @ K^T * scale (causal block skip)
    gemm_hmma<false><<<dim3(SEQ/128, SEQ/128, NH), gblk, 196608>>>(
        (const uint16_t*)qh, (const uint16_t*)ql, (const uint16_t*)kh, (const uint16_t*)kl,
        sc, HD, HD, HD, SEQ,
        (long long)SEQ * HD, (long long)SEQ * HD, (long long)SEQ * SEQ, GROUPS,
        ATT_SCALE, 1);

    // 8) softmax -> bf16 P planes
    softmax_kernel<<<dim3(SEQ, NH), blk>>>(sc, ph, pl);

    // 9) attn = P @ V (causal K limit)
    gemm_hmma<false><<<dim3(HD/128, SEQ/128, NH), gblk, 196608>>>(
        (const uint16_t*)ph, (const uint16_t*)pl, (const uint16_t*)vTh, (const uint16_t*)vTl,
        at, SEQ, SEQ, SEQ, HD,
        (long long)SEQ * SEQ, (long long)HD * SEQ, (long long)SEQ * HD, GROUPS,
        1.f, 2);

    // 10) gating -> fp16 planes
    gate_kernel<<<(unsigned)(((size_t)SEQ * NH * HD / 4 + 255) / 256), blk>>>(at, qkv, gth, gtl);

    // 11) hidden_out = gated @ o_w^T  (fp16 2-term)
    gemm_hmma<true><<<dim3(HID/128, SEQ/128, 1), gblk, 147456>>>(
        (const uint16_t*)gth, (const uint16_t*)gtl, (const uint16_t*)owh, nullptr,
        hidden_out, NH*HD, NH*HD, NH*HD, HID, 0, 0, 0, 1, 1.f, 0);
}

// round 7
// speedup vs baseline: 1.3455x; 1.1963x over previous
#include <cuda_runtime.h>
#include <cuda_bf16.h>
#include <cuda_fp16.h>
#include <cstdint>
#include <math.h>

// ---------------- problem constants ----------------
#define SEQ   2048
#define HID   2048
#define NH    16
#define NKV   2
#define HD    256
#define MAXS  4096
#define RD    64
#define GROUPS 8
#define ATT_SCALE 0.0625f
#define EPSV  1e-6f
#define NQKV  9216

typedef __nv_bfloat16 bf16;

// ---------------- scratch ----------------
__device__ __align__(1024) float g_qkv  [(size_t)SEQ * NQKV];
__device__ __align__(1024) float g_scores[(size_t)NH * SEQ * SEQ];
__device__ __align__(1024) float g_attn [(size_t)NH * SEQ * HD];

__device__ __align__(1024) __half g_hid_h[(size_t)SEQ * HID],  g_hid_l[(size_t)SEQ * HID];
__device__ __align__(1024) __half g_wqkv [(size_t)NQKV * HID];           // single fp16 plane
__device__ __align__(1024) __half g_ow   [(size_t)HID * NH*HD];          // single fp16 plane
__device__ __align__(1024) bf16 g_q_h  [(size_t)NH*SEQ*HD],    g_q_l  [(size_t)NH*SEQ*HD];
__device__ __align__(1024) bf16 g_k_h  [(size_t)NKV*SEQ*HD],   g_k_l  [(size_t)NKV*SEQ*HD];
__device__ __align__(1024) __half g_vT [(size_t)NKV*HD*SEQ];             // single fp16 plane
__device__ __align__(1024) __half g_p_h[(size_t)NH*SEQ*SEQ],   g_p_l[(size_t)NH*SEQ*SEQ];
__device__ __align__(1024) __half g_gt_h[(size_t)SEQ * NH*HD], g_gt_l[(size_t)SEQ * NH*HD];

// ---------------- PTX helpers ----------------
__device__ __forceinline__ uint32_t smem_u32(const void* p) {
    uint32_t a;
    asm("{ .reg .u64 t; cvta.to.shared.u64 t, %1; cvt.u32.u64 %0, t; }" : "=r"(a) : "l"(p));
    return a;
}
#define CP_ASYNC16(dst, src) \
    asm volatile("cp.async.cg.shared.global [%0], [%1], 16;" :: "r"(dst), "l"(src) : "memory")
#define CP_COMMIT() asm volatile("cp.async.commit_group;" ::: "memory")
#define CP_WAIT(n)  asm volatile("cp.async.wait_group %0;" :: "n"(n) : "memory")

#define LDSM_X4(r0, r1, r2, r3, addr) \
    asm volatile("ldmatrix.sync.aligned.m8n8.x4.shared.b16 {%0,%1,%2,%3}, [%4];" \
        : "=r"(r0), "=r"(r1), "=r"(r2), "=r"(r3) : "r"(addr))

#define MMA_BF16(d, a, b0v, b1v) \
    asm volatile("mma.sync.aligned.m16n8k16.row.col.f32.bf16.bf16.f32 " \
        "{%0,%1,%2,%3}, {%4,%5,%6,%7}, {%8,%9}, {%0,%1,%2,%3};" \
        : "+f"((d)[0]), "+f"((d)[1]), "+f"((d)[2]), "+f"((d)[3]) \
        : "r"((a)[0]), "r"((a)[1]), "r"((a)[2]), "r"((a)[3]), "r"(b0v), "r"(b1v))

#define MMA_F16(d, a, b0v, b1v) \
    asm volatile("mma.sync.aligned.m16n8k16.row.col.f32.f16.f16.f32 " \
        "{%0,%1,%2,%3}, {%4,%5,%6,%7}, {%8,%9}, {%0,%1,%2,%3};" \
        : "+f"((d)[0]), "+f"((d)[1]), "+f"((d)[2]), "+f"((d)[3]) \
        : "r"((a)[0]), "r"((a)[1]), "r"((a)[2]), "r"((a)[3]), "r"(b0v), "r"(b1v))

// ---------------- pack helpers ----------------
__device__ __forceinline__ uint32_t pack_hi2(float a, float b, float& la, float& lb) {
    bf16 ha = __float2bfloat16(a), hb = __float2bfloat16(b);
    la = a - __bfloat162float(ha);
    lb = b - __bfloat162float(hb);
    return (uint32_t)__bfloat16_as_ushort(ha) | ((uint32_t)__bfloat16_as_ushort(hb) << 16);
}
__device__ __forceinline__ uint32_t pack2(float a, float b) {
    return (uint32_t)__bfloat16_as_ushort(__float2bfloat16(a)) |
           ((uint32_t)__bfloat16_as_ushort(__float2bfloat16(b)) << 16);
}
__device__ __forceinline__ uint32_t packh2(float a, float b) {
    __half2 h = __floats2half2_rn(a, b);
    return *reinterpret_cast<uint32_t*>(&h);
}
__device__ __forceinline__ uint32_t packh_hi2(float a, float b, float& la, float& lb) {
    __half ha = __float2half_rn(a), hb = __float2half_rn(b);
    la = a - __half2float(ha);
    lb = b - __half2float(hb);
    __half2 h2 = __halves2half2(ha, hb);
    return *reinterpret_cast<uint32_t*>(&h2);
}

// ---------------- split-precision HMMA GEMM, 3-stage pipeline ----------------
// F16_2T=false: bf16 3-term (AhBh+AhBl+AlBh), 4 planes/chunk, 192KB smem.
// F16_2T=true : fp16 2-term (AhBh+AlBh), B single plane, 3 planes/chunk, 144KB.
// mode 0 plain; 1 causal block-skip; 2 causal K-limit.
template<bool F16_2T>
__global__ __launch_bounds__(512, 1)
void gemm_hmma(const uint16_t* __restrict__ Ah, const uint16_t* __restrict__ Al,
               const uint16_t* __restrict__ Bh, const uint16_t* __restrict__ Bl,
               float* __restrict__ C,
               int K, int lda, int ldb, int ldc,
               long long sA, long long sB, long long sC, int bDiv,
               float alpha, int mode)
{
    constexpr int NPLANES = F16_2T ? 3 : 4;
    constexpr uint32_t STG = NPLANES * 16384u;

    const int bx = blockIdx.x, by = blockIdx.y, bz = blockIdx.z;
    if (mode == 1 && bx > by) return;
    const int Keff = (mode == 2) ? min(K, (by + 1) * 128) : K;
    const int nch = Keff >> 6;

    extern __shared__ char smem[];
    const uint32_t sb = smem_u32(smem);

    const uint16_t* srcs[4] = { Ah + (size_t)bz * sA, Al + (size_t)bz * sA,
                                Bh + (size_t)(bz / bDiv) * sB,
                                F16_2T ? nullptr : Bl + (size_t)(bz / bDiv) * sB };
    const int lds[4] = { lda, lda, ldb, ldb };
    const int rb [4] = { by * 128, by * 128, bx * 128, bx * 128 };

    const int tid = threadIdx.x, lane = tid & 31, wid = tid >> 5;
    const int wm = wid >> 2, wn = wid & 3;

    float acc[2][4][4];
    #pragma unroll
    for (int mt = 0; mt < 2; ++mt)
        #pragma unroll
        for (int nt = 0; nt < 4; ++nt)
            #pragma unroll
            for (int r = 0; r < 4; ++r) acc[mt][nt][r] = 0.f;

    auto issue = [&](int ch) {
        const uint32_t dbase = sb + (uint32_t)(ch % 3) * STG;
        const int kt = ch << 6;
        #pragma unroll
        for (int p = 0; p < NPLANES; ++p) {
            #pragma unroll
            for (int i = 0; i < 2; ++i) {
                const int u = tid + i * 512;
                const int r = u >> 3, c = u & 7;
                const uint16_t* s = srcs[p] + (size_t)(rb[p] + r) * lds[p] + kt + c * 8;
                const uint32_t d = dbase + (uint32_t)(p * 16384 + r * 128 +
                                   ((c * 16) ^ ((r & 7) << 4)));
                CP_ASYNC16(d, (const void*)s);
            }
        }
        CP_COMMIT();
    };

    issue(0);
    issue(1);
    for (int ch = 0; ch < nch; ++ch) {
        if (ch + 1 < nch) { CP_WAIT(1); }
        else              { CP_WAIT(0); }
        __syncthreads();
        if (ch + 2 < nch) issue(ch + 2);

        const uint32_t b0 = sb + (uint32_t)(ch % 3) * STG;

        #pragma unroll
        for (int ks = 0; ks < 4; ++ks) {
            const uint32_t colk = (uint32_t)(ks * 32 + ((lane >> 4) << 4));
            uint32_t ah[2][4], alr[2][4], bh[2][4], blr[2][4];
            #pragma unroll
            for (int mt = 0; mt < 2; ++mt) {
                const int row = wm * 32 + mt * 16 + (lane & 15);
                const uint32_t a0 = b0 + (uint32_t)(row * 128) + (colk ^ ((row & 7) << 4));
                LDSM_X4(ah [mt][0], ah [mt][1], ah [mt][2], ah [mt][3], a0);
                LDSM_X4(alr[mt][0], alr[mt][1], alr[mt][2], alr[mt][3], a0 + 16384u);
            }
            #pragma unroll
            for (int pr = 0; pr < 2; ++pr) {
                const int row = wn * 32 + pr * 16 + (lane & 15);
                const uint32_t a0 = b0 + 32768u + (uint32_t)(row * 128) + (colk ^ ((row & 7) << 4));
                LDSM_X4(bh[pr][0], bh[pr][1], bh[pr][2], bh[pr][3], a0);
                if (!F16_2T)
                    LDSM_X4(blr[pr][0], blr[pr][1], blr[pr][2], blr[pr][3], a0 + 16384u);
            }
            if (F16_2T) {
                #pragma unroll
                for (int term = 0; term < 2; ++term) {
                    #pragma unroll
                    for (int mt = 0; mt < 2; ++mt) {
                        #pragma unroll
                        for (int nt = 0; nt < 4; ++nt) {
                            const uint32_t* af = (term == 1) ? alr[mt] : ah[mt];
                            const uint32_t b0v = bh[nt >> 1][nt & 1];
                            const uint32_t b1v = bh[nt >> 1][(nt & 1) + 2];
                            MMA_F16(acc[mt][nt], af, b0v, b1v);
                        }
                    }
                }
            } else {
                #pragma unroll
                for (int term = 0; term < 3; ++term) {
                    #pragma unroll
                    for (int mt = 0; mt < 2; ++mt) {
                        #pragma unroll
                        for (int nt = 0; nt < 4; ++nt) {
                            const uint32_t* af = (term == 2) ? alr[mt] : ah[mt];
                            const uint32_t b0v = (term == 1) ? blr[nt >> 1][nt & 1]
                                                             : bh [nt >> 1][nt & 1];
                            const uint32_t b1v = (term == 1) ? blr[nt >> 1][(nt & 1) + 2]
                                                             : bh [nt >> 1][(nt & 1) + 2];
                            MMA_BF16(acc[mt][nt], af, b0v, b1v);
                        }
                    }
                }
            }
        }
    }

    float* pC = C + (size_t)bz * sC;
    #pragma unroll
    for (int mt = 0; mt < 2; ++mt) {
        #pragma unroll
        for (int nt = 0; nt < 4; ++nt) {
            const int row = by * 128 + wm * 32 + mt * 16 + (lane >> 2);
            const int col = bx * 128 + wn * 32 + nt * 8 + (lane & 3) * 2;
            float2 v0 = { acc[mt][nt][0] * alpha, acc[mt][nt][1] * alpha };
            float2 v1 = { acc[mt][nt][2] * alpha, acc[mt][nt][3] * alpha };
            *reinterpret_cast<float2*>(&pC[(size_t)row * ldc + col])       = v0;
            *reinterpret_cast<float2*>(&pC[(size_t)(row + 8) * ldc + col]) = v1;
        }
    }
}

// ---------------- weight split: all weights -> single fp16 plane ----------------
// quads: qw [0,4194304) kw [.,4456448) vw [.,4718592) ow [.,6815744)
__global__ void split_w_kernel(const float* __restrict__ qw, const float* __restrict__ kw,
                               const float* __restrict__ vw, const float* __restrict__ ow,
                               __half* __restrict__ wqkv, __half* __restrict__ owh)
{
    size_t i = (size_t)blockIdx.x * blockDim.x + threadIdx.x;
    if (i >= 6815744u) return;
    const float* src; size_t loc; __half* dst;
    if (i < 4194304u)      { src = qw; loc = i;            dst = wqkv; }
    else if (i < 4456448u) { src = kw; loc = i - 4194304u; dst = wqkv + 16777216u; }
    else if (i < 4718592u) { src = vw; loc = i - 4456448u; dst = wqkv + 17825792u; }
    else                   { src = ow; loc = i - 4718592u; dst = owh; }
    float4 v = reinterpret_cast<const float4*>(src)[loc];
    uint2 hh = { packh2(v.x, v.y), packh2(v.z, v.w) };
    reinterpret_cast<uint2*>(dst)[loc] = hh;
}

// ---------------- activation split: hidden -> fp16 hi/lo ----------------
__global__ void split_a_kernel(const float* __restrict__ x,
                               __half* __restrict__ hi, __half* __restrict__ lo)
{
    size_t i = (size_t)blockIdx.x * blockDim.x + threadIdx.x;
    if (i >= 1048576u) return;
    float4 v = reinterpret_cast<const float4*>(x)[i];
    float lx, ly, lz, lw2;
    uint2 hh, ll;
    hh.x = packh_hi2(v.x, v.y, lx, ly);
    hh.y = packh_hi2(v.z, v.w, lz, lw2);
    ll.x = packh2(lx, ly); ll.y = packh2(lz, lw2);
    reinterpret_cast<uint2*>(hi)[i] = hh;
    reinterpret_cast<uint2*>(lo)[i] = ll;
}

// ---------------- block reduce ----------------
__device__ __forceinline__ float blk_reduce(float v, bool do_max, float* sred,
                                            int tid, int lane, int wid) {
    #pragma unroll
    for (int o = 16; o > 0; o >>= 1) {
        float t = __shfl_xor_sync(0xffffffffu, v, o);
        v = do_max ? fmaxf(v, t) : (v + t);
    }
    if (lane == 0) sred[wid] = v;
    __syncthreads();
    if (tid == 0) {
        float r = sred[0];
        #pragma unroll
        for (int w = 1; w < 8; ++w) r = do_max ? fmaxf(r, sred[w]) : (r + sred[w]);
        sred[8] = r;
    }
    __syncthreads();
    float r = sred[8];
    __syncthreads();
    return r;
}

// ---------------- RMSNorm + RoPE for Q -> bf16 hi/lo ----------------
__global__ __launch_bounds__(256)
void q_norm_rope_kernel(const float* __restrict__ qkv,
                        const float* __restrict__ cosb, const float* __restrict__ sinb,
                        const float* __restrict__ qw,
                        bf16* __restrict__ qh, bf16* __restrict__ ql)
{
    const int s = blockIdx.x, h = blockIdx.y, d = threadIdx.x;
    const int lane = d & 31, wid = d >> 5;
    float x = qkv[(size_t)s * NQKV + h * 512 + d];
    __shared__ float sred[9];
    __shared__ float xs[256];
    float r = blk_reduce(x * x, false, sred, d, lane, wid);
    r = rsqrtf(r * (1.f / HD) + EPSV);
    float xn = x * r * (1.f + qw[d]);
    xs[d] = xn;
    __syncthreads();
    float o = xn;
    if (d < RD) {
        float rot = (d < RD / 2) ? -xs[d + RD / 2] : xs[d - RD / 2];
        o = xn * cosb[(size_t)s * RD + d] + rot * sinb[(size_t)s * RD + d];
    }
    size_t idx = ((size_t)h * SEQ + s) * HD + d;
    bf16 hv = __float2bfloat16(o);
    qh[idx] = hv;
    ql[idx] = __float2bfloat16(o - __bfloat162float(hv));
}

// ---------------- RMSNorm + RoPE for K; caches + planes ----------------
__global__ __launch_bounds__(256)
void kv_norm_rope_kernel(const float* __restrict__ qkv,
                         const float* __restrict__ cosb, const float* __restrict__ sinb,
                         const float* __restrict__ kw,
                         float* __restrict__ kcache, float* __restrict__ vcache,
                         bf16* __restrict__ kh, bf16* __restrict__ kl,
                         __half* __restrict__ vT)
{
    const int s = blockIdx.x, kv = blockIdx.y, d = threadIdx.x;
    const int lane = d & 31, wid = d >> 5;
    float x = qkv[(size_t)s * NQKV + 8192 + kv * 256 + d];
    float v = qkv[(size_t)s * NQKV + 8704 + kv * 256 + d];
    __shared__ float sred[9];
    __shared__ float xs[256];
    float r = blk_reduce(x * x, false, sred, d, lane, wid);
    r = rsqrtf(r * (1.f / HD) + EPSV);
    float xn = x * r * (1.f + kw[d]);
    xs[d] = xn;
    __syncthreads();
    float o = xn;
    if (d < RD) {
        float rot = (d < RD / 2) ? -xs[d + RD / 2] : xs[d - RD / 2];
        o = xn * cosb[(size_t)s * RD + d] + rot * sinb[(size_t)s * RD + d];
    }
    size_t cidx = ((size_t)kv * MAXS + s) * HD + d;
    kcache[cidx] = o;
    vcache[cidx] = v;
    size_t kidx = ((size_t)kv * SEQ + s) * HD + d;
    bf16 khv = __float2bfloat16(o);
    kh[kidx] = khv;
    kl[kidx] = __float2bfloat16(o - __bfloat162float(khv));
    vT[((size_t)kv * HD + d) * SEQ + s] = __float2half_rn(v);
}

// ---------------- zero pad caches rows SEQ..MAXS ----------------
__global__ void zero_pad_kernel(float* __restrict__ kcache, float* __restrict__ vcache)
{
    size_t idx = (size_t)blockIdx.x * blockDim.x + threadIdx.x;
    const size_t per_kv = (size_t)(MAXS - SEQ) * HD;
    if (idx >= (size_t)NKV * per_kv) return;
    size_t kv = idx / per_kv, rem = idx - kv * per_kv;
    size_t off = kv * (size_t)MAXS * HD + (size_t)SEQ * HD + rem;
    kcache[off] = 0.f;
    vcache[off] = 0.f;
}

// ---------------- causal softmax -> fp16 P hi/lo planes ----------------
__global__ __launch_bounds__(256)
void softmax_kernel(const float* __restrict__ scores,
                    __half* __restrict__ ph, __half* __restrict__ pl)
{
    const int i = blockIdx.x, h = blockIdx.y, tid = threadIdx.x;
    const int lane = tid & 31, wid = tid >> 5;
    const float* row = scores + ((size_t)h * SEQ + i) * SEQ;
    __half* prh = ph + ((size_t)h * SEQ + i) * SEQ;
    __half* prl = pl + ((size_t)h * SEQ + i) * SEQ;
    const int n = i + 1;
    const int end = ((i >> 7) + 1) << 7;
    const int j0 = tid * 8;
    __shared__ float sred[9];

    float v[8];
    if (j0 < end) {
        float4 a = *reinterpret_cast<const float4*>(row + j0);
        float4 b = *reinterpret_cast<const float4*>(row + j0 + 4);
        v[0]=a.x; v[1]=a.y; v[2]=a.z; v[3]=a.w;
        v[4]=b.x; v[5]=b.y; v[6]=b.z; v[7]=b.w;
    } else {
        #pragma unroll
        for (int e = 0; e < 8; ++e) v[e] = -1e30f;
    }

    float m = -1e30f;
    #pragma unroll
    for (int e = 0; e < 8; ++e) if (j0 + e < n) m = fmaxf(m, v[e]);
    m = blk_reduce(m, true, sred, tid, lane, wid);

    float sum = 0.f;
    #pragma unroll
    for (int e = 0; e < 8; ++e) {
        float p = (j0 + e < n) ? __expf(v[e] - m) : 0.f;
        v[e] = p;
        sum += p;
    }
    sum = blk_reduce(sum, false, sred, tid, lane, wid);
    const float inv = 1.f / sum;

    if (j0 < end) {
        uint4 hh, ll;
        float lo[8];
        float p0 = v[0]*inv, p1 = v[1]*inv, p2 = v[2]*inv, p3 = v[3]*inv;
        float p4 = v[4]*inv, p5 = v[5]*inv, p6 = v[6]*inv, p7 = v[7]*inv;
        hh.x = packh_hi2(p0, p1, lo[0], lo[1]);
        hh.y = packh_hi2(p2, p3, lo[2], lo[3]);
        hh.z = packh_hi2(p4, p5, lo[4], lo[5]);
        hh.w = packh_hi2(p6, p7, lo[6], lo[7]);
        ll.x = packh2(lo[0], lo[1]); ll.y = packh2(lo[2], lo[3]);
        ll.z = packh2(lo[4], lo[5]); ll.w = packh2(lo[6], lo[7]);
        *reinterpret_cast<uint4*>(prh + j0) = hh;
        *reinterpret_cast<uint4*>(prl + j0) = ll;
    }
}

// ---------------- gating -> fp16 hi/lo planes ----------------
__global__ void gate_kernel(const float* __restrict__ attn, const float* __restrict__ qkv,
                            __half* __restrict__ gh, __half* __restrict__ gl)
{
    size_t idx = (size_t)blockIdx.x * blockDim.x + threadIdx.x;
    if (idx >= (size_t)SEQ * NH * HD / 4) return;
    int s = (int)(idx >> 10);
    int r = (int)(idx & 1023);
    int h = r >> 6, dq = (r & 63) * 4;
    float4 a = *reinterpret_cast<const float4*>(&attn[((size_t)h * SEQ + s) * HD + dq]);
    float4 g = *reinterpret_cast<const float4*>(&qkv[(size_t)s * NQKV + h * 512 + 256 + dq]);
    float o0 = a.x * (1.f / (1.f + __expf(-g.x)));
    float o1 = a.y * (1.f / (1.f + __expf(-g.y)));
    float o2 = a.z * (1.f / (1.f + __expf(-g.z)));
    float o3 = a.w * (1.f / (1.f + __expf(-g.w)));
    float l0, l1, l2, l3;
    uint2 hh = { packh_hi2(o0, o1, l0, l1), packh_hi2(o2, o3, l2, l3) };
    uint2 ll = { packh2(l0, l1), packh2(l2, l3) };
    size_t o = (size_t)s * (NH * HD) + h * HD + dq;
    *reinterpret_cast<uint2*>(gh + o) = hh;
    *reinterpret_cast<uint2*>(gl + o) = ll;
}

// ---------------- launch ----------------
extern "C" void kernel_launch(void* const* d_in, const int* in_sizes, int n_in,
                              void* d_out, int out_size)
{
    const float* hidden = (const float*)d_in[0];
    const float* cosb   = (const float*)d_in[1];
    const float* sinb   = (const float*)d_in[2];
    const float* q_w    = (const float*)d_in[3];
    const float* k_w    = (const float*)d_in[4];
    const float* v_w    = (const float*)d_in[5];
    const float* o_w    = (const float*)d_in[6];
    const float* qnw    = (const float*)d_in[7];
    const float* knw    = (const float*)d_in[8];

    float* hidden_out = (float*)d_out;
    float* kcache = hidden_out + (size_t)SEQ * HID;
    float* vcache = kcache + (size_t)NKV * MAXS * HD;

    float *qkv, *sc, *at;
    __half *hidh, *hidl, *wqkv, *owh, *vT, *ph, *pl, *gth, *gtl;
    bf16 *qh, *ql, *kh, *kl;
    cudaGetSymbolAddress((void**)&qkv, g_qkv);
    cudaGetSymbolAddress((void**)&sc, g_scores);
    cudaGetSymbolAddress((void**)&at, g_attn);
    cudaGetSymbolAddress((void**)&hidh, g_hid_h); cudaGetSymbolAddress((void**)&hidl, g_hid_l);
    cudaGetSymbolAddress((void**)&wqkv, g_wqkv);
    cudaGetSymbolAddress((void**)&owh, g_ow);
    cudaGetSymbolAddress((void**)&qh, g_q_h);     cudaGetSymbolAddress((void**)&ql, g_q_l);
    cudaGetSymbolAddress((void**)&kh, g_k_h);     cudaGetSymbolAddress((void**)&kl, g_k_l);
    cudaGetSymbolAddress((void**)&vT, g_vT);
    cudaGetSymbolAddress((void**)&ph, g_p_h);     cudaGetSymbolAddress((void**)&pl, g_p_l);
    cudaGetSymbolAddress((void**)&gth, g_gt_h);   cudaGetSymbolAddress((void**)&gtl, g_gt_l);

    cudaFuncSetAttribute(gemm_hmma<false>, cudaFuncAttributeMaxDynamicSharedMemorySize, 196608);
    cudaFuncSetAttribute(gemm_hmma<true>,  cudaFuncAttributeMaxDynamicSharedMemorySize, 147456);

    dim3 blk(256);
    dim3 gblk(512);

    // 1) cache zero-pad
    zero_pad_kernel<<<(unsigned)(((size_t)NKV * (MAXS - SEQ) * HD + 255) / 256), blk>>>(kcache, vcache);
    // 2) weight split (single fp16 planes)
    split_w_kernel<<<26624, blk>>>(q_w, k_w, v_w, o_w, wqkv, owh);
    // 3) activation split (fp16 hi/lo)
    split_a_kernel<<<4096, blk>>>(hidden, hidh, hidl);

    // 4) fused qkv projection [2048 x 9216], fp16 2-term
    gemm_hmma<true><<<dim3(NQKV/128, SEQ/128, 1), gblk, 147456>>>(
        (const uint16_t*)hidh, (const uint16_t*)hidl, (const uint16_t*)wqkv, nullptr,
        qkv, HID, HID, HID, NQKV, 0, 0, 0, 1, 1.f, 0);

    // 5-6) norms + rope + caches
    q_norm_rope_kernel<<<dim3(SEQ, NH), blk>>>(qkv, cosb, sinb, qnw, qh, ql);
    kv_norm_rope_kernel<<<dim3(SEQ, NKV), blk>>>(qkv, cosb, sinb, knw,
                                                 kcache, vcache, kh, kl, vT);

    // 7) scores = Q @ K^T * scale (causal block skip), bf16 3-term
    gemm_hmma<false><<<dim3(SEQ/128, SEQ/128, NH), gblk, 196608>>>(
        (const uint16_t*)qh, (const uint16_t*)ql, (const uint16_t*)kh, (const uint16_t*)kl,
        sc, HD, HD, HD, SEQ,
        (long long)SEQ * HD, (long long)SEQ * HD, (long long)SEQ * SEQ, GROUPS,
        ATT_SCALE, 1);

    // 8) softmax -> fp16 P planes
    softmax_kernel<<<dim3(SEQ, NH), blk>>>(sc, ph, pl);

    // 9) attn = P @ V (causal K limit), fp16 2-term
    gemm_hmma<true><<<dim3(HD/128, SEQ/128, NH), gblk, 147456>>>(
        (const uint16_t*)ph, (const uint16_t*)pl, (const uint16_t*)vT, nullptr,
        at, SEQ, SEQ, SEQ, HD,
        (long long)SEQ * SEQ, (long long)HD * SEQ, (long long)SEQ * HD, GROUPS,
        1.f, 2);

    // 10) gating -> fp16 planes
    gate_kernel<<<(unsigned)(((size_t)SEQ * NH * HD / 4 + 255) / 256), blk>>>(at, qkv, gth, gtl);

    // 11) hidden_out = gated @ o_w^T, fp16 2-term
    gemm_hmma<true><<<dim3(HID/128, SEQ/128, 1), gblk, 147456>>>(
        (const uint16_t*)gth, (const uint16_t*)gtl, (const uint16_t*)owh, nullptr,
        hidden_out, NH*HD, NH*HD, NH*HD, HID, 0, 0, 0, 1, 1.f, 0);
}

// round 8
// speedup vs baseline: 1.3776x; 1.0239x over previous
#include <cuda_runtime.h>
#include <cuda_bf16.h>
#include <cuda_fp16.h>
#include <cstdint>
#include <math.h>

// ---------------- problem constants ----------------
#define SEQ   2048
#define HID   2048
#define NH    16
#define NKV   2
#define HD    256
#define MAXS  4096
#define RD    64
#define GROUPS 8
#define ATT_SCALE 0.0625f
#define EPSV  1e-6f
#define NQKV  9216

typedef __nv_bfloat16 bf16;

// ---------------- scratch ----------------
__device__ __align__(1024) float g_qkv  [(size_t)SEQ * NQKV];
__device__ __align__(1024) float g_scores[(size_t)NH * SEQ * SEQ];
__device__ __align__(1024) float g_attn [(size_t)NH * SEQ * HD];

__device__ __align__(1024) __half g_hid_h[(size_t)SEQ * HID],  g_hid_l[(size_t)SEQ * HID];
__device__ __align__(1024) __half g_wqkv [(size_t)NQKV * HID];
__device__ __align__(1024) __half g_ow   [(size_t)HID * NH*HD];
__device__ __align__(1024) bf16 g_q_h  [(size_t)NH*SEQ*HD],    g_q_l  [(size_t)NH*SEQ*HD];
__device__ __align__(1024) bf16 g_k_h  [(size_t)NKV*SEQ*HD],   g_k_l  [(size_t)NKV*SEQ*HD];
__device__ __align__(1024) __half g_vT [(size_t)NKV*HD*SEQ];
__device__ __align__(1024) __half g_p_h[(size_t)NH*SEQ*SEQ],   g_p_l[(size_t)NH*SEQ*SEQ];
__device__ __align__(1024) __half g_gt_h[(size_t)SEQ * NH*HD], g_gt_l[(size_t)SEQ * NH*HD];

// ---------------- PTX helpers ----------------
__device__ __forceinline__ uint32_t smem_u32(const void* p) {
    uint32_t a;
    asm("{ .reg .u64 t; cvta.to.shared.u64 t, %1; cvt.u32.u64 %0, t; }" : "=r"(a) : "l"(p));
    return a;
}
#define CP_ASYNC16(dst, src) \
    asm volatile("cp.async.cg.shared.global [%0], [%1], 16;" :: "r"(dst), "l"(src) : "memory")
#define CP_COMMIT() asm volatile("cp.async.commit_group;" ::: "memory")
#define CP_WAIT(n)  asm volatile("cp.async.wait_group %0;" :: "n"(n) : "memory")

#define LDSM_X4(r0, r1, r2, r3, addr) \
    asm volatile("ldmatrix.sync.aligned.m8n8.x4.shared.b16 {%0,%1,%2,%3}, [%4];" \
        : "=r"(r0), "=r"(r1), "=r"(r2), "=r"(r3) : "r"(addr))

#define MMA_BF16(d, a, b0v, b1v) \
    asm volatile("mma.sync.aligned.m16n8k16.row.col.f32.bf16.bf16.f32 " \
        "{%0,%1,%2,%3}, {%4,%5,%6,%7}, {%8,%9}, {%0,%1,%2,%3};" \
        : "+f"((d)[0]), "+f"((d)[1]), "+f"((d)[2]), "+f"((d)[3]) \
        : "r"((a)[0]), "r"((a)[1]), "r"((a)[2]), "r"((a)[3]), "r"(b0v), "r"(b1v))

#define MMA_F16(d, a, b0v, b1v) \
    asm volatile("mma.sync.aligned.m16n8k16.row.col.f32.f16.f16.f32 " \
        "{%0,%1,%2,%3}, {%4,%5,%6,%7}, {%8,%9}, {%0,%1,%2,%3};" \
        : "+f"((d)[0]), "+f"((d)[1]), "+f"((d)[2]), "+f"((d)[3]) \
        : "r"((a)[0]), "r"((a)[1]), "r"((a)[2]), "r"((a)[3]), "r"(b0v), "r"(b1v))

// ---------------- pack helpers ----------------
__device__ __forceinline__ uint32_t pack_hi2(float a, float b, float& la, float& lb) {
    bf16 ha = __float2bfloat16(a), hb = __float2bfloat16(b);
    la = a - __bfloat162float(ha);
    lb = b - __bfloat162float(hb);
    return (uint32_t)__bfloat16_as_ushort(ha) | ((uint32_t)__bfloat16_as_ushort(hb) << 16);
}
__device__ __forceinline__ uint32_t pack2(float a, float b) {
    return (uint32_t)__bfloat16_as_ushort(__float2bfloat16(a)) |
           ((uint32_t)__bfloat16_as_ushort(__float2bfloat16(b)) << 16);
}
__device__ __forceinline__ uint32_t packh2(float a, float b) {
    __half2 h = __floats2half2_rn(a, b);
    return *reinterpret_cast<uint32_t*>(&h);
}
__device__ __forceinline__ uint32_t packh_hi2(float a, float b, float& la, float& lb) {
    __half ha = __float2half_rn(a), hb = __float2half_rn(b);
    la = a - __half2float(ha);
    lb = b - __half2float(hb);
    __half2 h2 = __halves2half2(ha, hb);
    return *reinterpret_cast<uint32_t*>(&h2);
}

// ---------------- bf16 3-term HMMA GEMM, 128x128 tile (scores) ----------------
__global__ __launch_bounds__(512, 1)
void gemm_hmma(const uint16_t* __restrict__ Ah, const uint16_t* __restrict__ Al,
               const uint16_t* __restrict__ Bh, const uint16_t* __restrict__ Bl,
               float* __restrict__ C,
               int K, int lda, int ldb, int ldc,
               long long sA, long long sB, long long sC, int bDiv,
               float alpha, int mode)
{
    constexpr uint32_t STG = 65536u;

    const int bx = blockIdx.x, by = blockIdx.y, bz = blockIdx.z;
    if (mode == 1 && bx > by) return;
    const int Keff = (mode == 2) ? min(K, (by + 1) * 128) : K;
    const int nch = Keff >> 6;

    extern __shared__ char smem[];
    const uint32_t sb = smem_u32(smem);

    const uint16_t* srcs[4] = { Ah + (size_t)bz * sA, Al + (size_t)bz * sA,
                                Bh + (size_t)(bz / bDiv) * sB, Bl + (size_t)(bz / bDiv) * sB };
    const int lds[4] = { lda, lda, ldb, ldb };
    const int rb [4] = { by * 128, by * 128, bx * 128, bx * 128 };

    const int tid = threadIdx.x, lane = tid & 31, wid = tid >> 5;
    const int wm = wid >> 2, wn = wid & 3;

    float acc[2][4][4];
    #pragma unroll
    for (int mt = 0; mt < 2; ++mt)
        #pragma unroll
        for (int nt = 0; nt < 4; ++nt)
            #pragma unroll
            for (int r = 0; r < 4; ++r) acc[mt][nt][r] = 0.f;

    auto issue = [&](int ch) {
        const uint32_t dbase = sb + (uint32_t)(ch % 3) * STG;
        const int kt = ch << 6;
        #pragma unroll
        for (int p = 0; p < 4; ++p) {
            #pragma unroll
            for (int i = 0; i < 2; ++i) {
                const int u = tid + i * 512;
                const int r = u >> 3, c = u & 7;
                const uint16_t* s = srcs[p] + (size_t)(rb[p] + r) * lds[p] + kt + c * 8;
                const uint32_t d = dbase + (uint32_t)(p * 16384 + r * 128 +
                                   ((c * 16) ^ ((r & 7) << 4)));
                CP_ASYNC16(d, (const void*)s);
            }
        }
        CP_COMMIT();
    };

    issue(0);
    issue(1);
    for (int ch = 0; ch < nch; ++ch) {
        if (ch + 1 < nch) { CP_WAIT(1); }
        else              { CP_WAIT(0); }
        __syncthreads();
        if (ch + 2 < nch) issue(ch + 2);

        const uint32_t b0 = sb + (uint32_t)(ch % 3) * STG;

        #pragma unroll
        for (int ks = 0; ks < 4; ++ks) {
            const uint32_t colk = (uint32_t)(ks * 32 + ((lane >> 4) << 4));
            uint32_t ah[2][4], alr[2][4], bh[2][4], blr[2][4];
            #pragma unroll
            for (int mt = 0; mt < 2; ++mt) {
                const int row = wm * 32 + mt * 16 + (lane & 15);
                const uint32_t a0 = b0 + (uint32_t)(row * 128) + (colk ^ ((row & 7) << 4));
                LDSM_X4(ah [mt][0], ah [mt][1], ah [mt][2], ah [mt][3], a0);
                LDSM_X4(alr[mt][0], alr[mt][1], alr[mt][2], alr[mt][3], a0 + 16384u);
            }
            #pragma unroll
            for (int pr = 0; pr < 2; ++pr) {
                const int row = wn * 32 + pr * 16 + (lane & 15);
                const uint32_t a0 = b0 + 32768u + (uint32_t)(row * 128) + (colk ^ ((row & 7) << 4));
                LDSM_X4(bh [pr][0], bh [pr][1], bh [pr][2], bh [pr][3], a0);
                LDSM_X4(blr[pr][0], blr[pr][1], blr[pr][2], blr[pr][3], a0 + 16384u);
            }
            #pragma unroll
            for (int term = 0; term < 3; ++term) {
                #pragma unroll
                for (int mt = 0; mt < 2; ++mt) {
                    #pragma unroll
                    for (int nt = 0; nt < 4; ++nt) {
                        const uint32_t* af = (term == 2) ? alr[mt] : ah[mt];
                        const uint32_t b0v = (term == 1) ? blr[nt >> 1][nt & 1]
                                                         : bh [nt >> 1][nt & 1];
                        const uint32_t b1v = (term == 1) ? blr[nt >> 1][(nt & 1) + 2]
                                                         : bh [nt >> 1][(nt & 1) + 2];
                        MMA_BF16(acc[mt][nt], af, b0v, b1v);
                    }
                }
            }
        }
    }

    float* pC = C + (size_t)bz * sC;
    #pragma unroll
    for (int mt = 0; mt < 2; ++mt) {
        #pragma unroll
        for (int nt = 0; nt < 4; ++nt) {
            const int row = by * 128 + wm * 32 + mt * 16 + (lane >> 2);
            const int col = bx * 128 + wn * 32 + nt * 8 + (lane & 3) * 2;
            float2 v0 = { acc[mt][nt][0] * alpha, acc[mt][nt][1] * alpha };
            float2 v1 = { acc[mt][nt][2] * alpha, acc[mt][nt][3] * alpha };
            *reinterpret_cast<float2*>(&pC[(size_t)row * ldc + col])       = v0;
            *reinterpret_cast<float2*>(&pC[(size_t)(row + 8) * ldc + col]) = v1;
        }
    }
}

// ---------------- fp16 2-term HMMA GEMM, 128x256 tile, 3-stage ----------------
// C[M,N] = alpha * (Ah+Al) * Bh^T ; per-chunk smem: Ah 16K | Al 16K | B 32K = 64K
// mode 0 plain; 2 causal K-limit.
__global__ __launch_bounds__(512, 1)
void gemm_hmma_wide(const uint16_t* __restrict__ Ah, const uint16_t* __restrict__ Al,
                    const uint16_t* __restrict__ Bh,
                    float* __restrict__ C,
                    int K, int lda, int ldb, int ldc,
                    long long sA, long long sB, long long sC, int bDiv,
                    float alpha, int mode)
{
    constexpr uint32_t STG = 65536u;

    const int bx = blockIdx.x, by = blockIdx.y, bz = blockIdx.z;
    const int Keff = (mode == 2) ? min(K, (by + 1) * 128) : K;
    const int nch = Keff >> 6;

    extern __shared__ char smem[];
    const uint32_t sb = smem_u32(smem);

    const uint16_t* pAh = Ah + (size_t)bz * sA;
    const uint16_t* pAl = Al + (size_t)bz * sA;
    const uint16_t* pB  = Bh + (size_t)(bz / bDiv) * sB;
    const int rm = by * 128, rn = bx * 256;

    const int tid = threadIdx.x, lane = tid & 31, wid = tid >> 5;
    const int wm = wid >> 2, wn = wid & 3;

    float acc[2][8][4];
    #pragma unroll
    for (int mt = 0; mt < 2; ++mt)
        #pragma unroll
        for (int nt = 0; nt < 8; ++nt)
            #pragma unroll
            for (int r = 0; r < 4; ++r) acc[mt][nt][r] = 0.f;

    auto issue = [&](int ch) {
        const uint32_t dbase = sb + (uint32_t)(ch % 3) * STG;
        const int kt = ch << 6;
        // A hi/lo: 128 rows x 128B each
        #pragma unroll
        for (int p = 0; p < 2; ++p) {
            const uint16_t* ap = p ? pAl : pAh;
            #pragma unroll
            for (int i = 0; i < 2; ++i) {
                const int u = tid + i * 512;
                const int r = u >> 3, c = u & 7;
                const uint16_t* s = ap + (size_t)(rm + r) * lda + kt + c * 8;
                const uint32_t d = dbase + (uint32_t)(p * 16384 + r * 128 +
                                   ((c * 16) ^ ((r & 7) << 4)));
                CP_ASYNC16(d, (const void*)s);
            }
        }
        // B: 256 rows x 128B
        #pragma unroll
        for (int i = 0; i < 4; ++i) {
            const int u = tid + i * 512;         // 0..2047
            const int r = u >> 3, c = u & 7;
            const uint16_t* s = pB + (size_t)(rn + r) * ldb + kt + c * 8;
            const uint32_t d = dbase + 32768u + (uint32_t)(r * 128 +
                               ((c * 16) ^ ((r & 7) << 4)));
            CP_ASYNC16(d, (const void*)s);
        }
        CP_COMMIT();
    };

    issue(0);
    issue(1);
    for (int ch = 0; ch < nch; ++ch) {
        if (ch + 1 < nch) { CP_WAIT(1); }
        else              { CP_WAIT(0); }
        __syncthreads();
        if (ch + 2 < nch) issue(ch + 2);

        const uint32_t b0 = sb + (uint32_t)(ch % 3) * STG;

        #pragma unroll
        for (int ks = 0; ks < 4; ++ks) {
            const uint32_t colk = (uint32_t)(ks * 32 + ((lane >> 4) << 4));
            uint32_t ah[2][4], alr[2][4], bh[4][4];
            #pragma unroll
            for (int mt = 0; mt < 2; ++mt) {
                const int row = wm * 32 + mt * 16 + (lane & 15);
                const uint32_t a0 = b0 + (uint32_t)(row * 128) + (colk ^ ((row & 7) << 4));
                LDSM_X4(ah [mt][0], ah [mt][1], ah [mt][2], ah [mt][3], a0);
                LDSM_X4(alr[mt][0], alr[mt][1], alr[mt][2], alr[mt][3], a0 + 16384u);
            }
            #pragma unroll
            for (int pr = 0; pr < 4; ++pr) {
                const int row = wn * 64 + pr * 16 + (lane & 15);
                const uint32_t a0 = b0 + 32768u + (uint32_t)(row * 128) + (colk ^ ((row & 7) << 4));
                LDSM_X4(bh[pr][0], bh[pr][1], bh[pr][2], bh[pr][3], a0);
            }
            #pragma unroll
            for (int term = 0; term < 2; ++term) {
                #pragma unroll
                for (int mt = 0; mt < 2; ++mt) {
                    #pragma unroll
                    for (int nt = 0; nt < 8; ++nt) {
                        const uint32_t* af = (term == 1) ? alr[mt] : ah[mt];
                        const uint32_t b0v = bh[nt >> 1][nt & 1];
                        const uint32_t b1v = bh[nt >> 1][(nt & 1) + 2];
                        MMA_F16(acc[mt][nt], af, b0v, b1v);
                    }
                }
            }
        }
    }

    float* pC = C + (size_t)bz * sC;
    #pragma unroll
    for (int mt = 0; mt < 2; ++mt) {
        #pragma unroll
        for (int nt = 0; nt < 8; ++nt) {
            const int row = rm + wm * 32 + mt * 16 + (lane >> 2);
            const int col = rn + wn * 64 + nt * 8 + (lane & 3) * 2;
            float2 v0 = { acc[mt][nt][0] * alpha, acc[mt][nt][1] * alpha };
            float2 v1 = { acc[mt][nt][2] * alpha, acc[mt][nt][3] * alpha };
            *reinterpret_cast<float2*>(&pC[(size_t)row * ldc + col])       = v0;
            *reinterpret_cast<float2*>(&pC[(size_t)(row + 8) * ldc + col]) = v1;
        }
    }
}

// ---------------- weight split: all weights -> single fp16 plane ----------------
__global__ void split_w_kernel(const float* __restrict__ qw, const float* __restrict__ kw,
                               const float* __restrict__ vw, const float* __restrict__ ow,
                               __half* __restrict__ wqkv, __half* __restrict__ owh)
{
    size_t i = (size_t)blockIdx.x * blockDim.x + threadIdx.x;
    if (i >= 6815744u) return;
    const float* src; size_t loc; __half* dst;
    if (i < 4194304u)      { src = qw; loc = i;            dst = wqkv; }
    else if (i < 4456448u) { src = kw; loc = i - 4194304u; dst = wqkv + 16777216u; }
    else if (i < 4718592u) { src = vw; loc = i - 4456448u; dst = wqkv + 17825792u; }
    else                   { src = ow; loc = i - 4718592u; dst = owh; }
    float4 v = reinterpret_cast<const float4*>(src)[loc];
    uint2 hh = { packh2(v.x, v.y), packh2(v.z, v.w) };
    reinterpret_cast<uint2*>(dst)[loc] = hh;
}

// ---------------- activation split: hidden -> fp16 hi/lo ----------------
__global__ void split_a_kernel(const float* __restrict__ x,
                               __half* __restrict__ hi, __half* __restrict__ lo)
{
    size_t i = (size_t)blockIdx.x * blockDim.x + threadIdx.x;
    if (i >= 1048576u) return;
    float4 v = reinterpret_cast<const float4*>(x)[i];
    float lx, ly, lz, lw2;
    uint2 hh, ll;
    hh.x = packh_hi2(v.x, v.y, lx, ly);
    hh.y = packh_hi2(v.z, v.w, lz, lw2);
    ll.x = packh2(lx, ly); ll.y = packh2(lz, lw2);
    reinterpret_cast<uint2*>(hi)[i] = hh;
    reinterpret_cast<uint2*>(lo)[i] = ll;
}

// ---------------- block reduce ----------------
__device__ __forceinline__ float blk_reduce(float v, bool do_max, float* sred,
                                            int tid, int lane, int wid) {
    #pragma unroll
    for (int o = 16; o > 0; o >>= 1) {
        float t = __shfl_xor_sync(0xffffffffu, v, o);
        v = do_max ? fmaxf(v, t) : (v + t);
    }
    if (lane == 0) sred[wid] = v;
    __syncthreads();
    if (tid == 0) {
        float r = sred[0];
        #pragma unroll
        for (int w = 1; w < 8; ++w) r = do_max ? fmaxf(r, sred[w]) : (r + sred[w]);
        sred[8] = r;
    }
    __syncthreads();
    float r = sred[8];
    __syncthreads();
    return r;
}

// ---------------- RMSNorm + RoPE for Q -> bf16 hi/lo ----------------
__global__ __launch_bounds__(256)
void q_norm_rope_kernel(const float* __restrict__ qkv,
                        const float* __restrict__ cosb, const float* __restrict__ sinb,
                        const float* __restrict__ qw,
                        bf16* __restrict__ qh, bf16* __restrict__ ql)
{
    const int s = blockIdx.x, h = blockIdx.y, d = threadIdx.x;
    const int lane = d & 31, wid = d >> 5;
    float x = qkv[(size_t)s * NQKV + h * 512 + d];
    __shared__ float sred[9];
    __shared__ float xs[256];
    float r = blk_reduce(x * x, false, sred, d, lane, wid);
    r = rsqrtf(r * (1.f / HD) + EPSV);
    float xn = x * r * (1.f + qw[d]);
    xs[d] = xn;
    __syncthreads();
    float o = xn;
    if (d < RD) {
        float rot = (d < RD / 2) ? -xs[d + RD / 2] : xs[d - RD / 2];
        o = xn * cosb[(size_t)s * RD + d] + rot * sinb[(size_t)s * RD + d];
    }
    size_t idx = ((size_t)h * SEQ + s) * HD + d;
    bf16 hv = __float2bfloat16(o);
    qh[idx] = hv;
    ql[idx] = __float2bfloat16(o - __bfloat162float(hv));
}

// ---------------- RMSNorm + RoPE for K; caches + planes ----------------
__global__ __launch_bounds__(256)
void kv_norm_rope_kernel(const float* __restrict__ qkv,
                         const float* __restrict__ cosb, const float* __restrict__ sinb,
                         const float* __restrict__ kw,
                         float* __restrict__ kcache, float* __restrict__ vcache,
                         bf16* __restrict__ kh, bf16* __restrict__ kl,
                         __half* __restrict__ vT)
{
    const int s = blockIdx.x, kv = blockIdx.y, d = threadIdx.x;
    const int lane = d & 31, wid = d >> 5;
    float x = qkv[(size_t)s * NQKV + 8192 + kv * 256 + d];
    float v = qkv[(size_t)s * NQKV + 8704 + kv * 256 + d];
    __shared__ float sred[9];
    __shared__ float xs[256];
    float r = blk_reduce(x * x, false, sred, d, lane, wid);
    r = rsqrtf(r * (1.f / HD) + EPSV);
    float xn = x * r * (1.f + kw[d]);
    xs[d] = xn;
    __syncthreads();
    float o = xn;
    if (d < RD) {
        float rot = (d < RD / 2) ? -xs[d + RD / 2] : xs[d - RD / 2];
        o = xn * cosb[(size_t)s * RD + d] + rot * sinb[(size_t)s * RD + d];
    }
    size_t cidx = ((size_t)kv * MAXS + s) * HD + d;
    kcache[cidx] = o;
    vcache[cidx] = v;
    size_t kidx = ((size_t)kv * SEQ + s) * HD + d;
    bf16 khv = __float2bfloat16(o);
    kh[kidx] = khv;
    kl[kidx] = __float2bfloat16(o - __bfloat162float(khv));
    vT[((size_t)kv * HD + d) * SEQ + s] = __float2half_rn(v);
}

// ---------------- zero pad caches rows SEQ..MAXS ----------------
__global__ void zero_pad_kernel(float* __restrict__ kcache, float* __restrict__ vcache)
{
    size_t idx = (size_t)blockIdx.x * blockDim.x + threadIdx.x;
    const size_t per_kv = (size_t)(MAXS - SEQ) * HD;
    if (idx >= (size_t)NKV * per_kv) return;
    size_t kv = idx / per_kv, rem = idx - kv * per_kv;
    size_t off = kv * (size_t)MAXS * HD + (size_t)SEQ * HD + rem;
    kcache[off] = 0.f;
    vcache[off] = 0.f;
}

// ---------------- causal softmax -> fp16 P hi/lo planes ----------------
__global__ __launch_bounds__(256)
void softmax_kernel(const float* __restrict__ scores,
                    __half* __restrict__ ph, __half* __restrict__ pl)
{
    const int i = blockIdx.x, h = blockIdx.y, tid = threadIdx.x;
    const int lane = tid & 31, wid = tid >> 5;
    const float* row = scores + ((size_t)h * SEQ + i) * SEQ;
    __half* prh = ph + ((size_t)h * SEQ + i) * SEQ;
    __half* prl = pl + ((size_t)h * SEQ + i) * SEQ;
    const int n = i + 1;
    const int end = ((i >> 7) + 1) << 7;
    const int j0 = tid * 8;
    __shared__ float sred[9];

    float v[8];
    if (j0 < end) {
        float4 a = *reinterpret_cast<const float4*>(row + j0);
        float4 b = *reinterpret_cast<const float4*>(row + j0 + 4);
        v[0]=a.x; v[1]=a.y; v[2]=a.z; v[3]=a.w;
        v[4]=b.x; v[5]=b.y; v[6]=b.z; v[7]=b.w;
    } else {
        #pragma unroll
        for (int e = 0; e < 8; ++e) v[e] = -1e30f;
    }

    float m = -1e30f;
    #pragma unroll
    for (int e = 0; e < 8; ++e) if (j0 + e < n) m = fmaxf(m, v[e]);
    m = blk_reduce(m, true, sred, tid, lane, wid);

    float sum = 0.f;
    #pragma unroll
    for (int e = 0; e < 8; ++e) {
        float p = (j0 + e < n) ? __expf(v[e] - m) : 0.f;
        v[e] = p;
        sum += p;
    }
    sum = blk_reduce(sum, false, sred, tid, lane, wid);
    const float inv = 1.f / sum;

    if (j0 < end) {
        uint4 hh, ll;
        float lo[8];
        float p0 = v[0]*inv, p1 = v[1]*inv, p2 = v[2]*inv, p3 = v[3]*inv;
        float p4 = v[4]*inv, p5 = v[5]*inv, p6 = v[6]*inv, p7 = v[7]*inv;
        hh.x = packh_hi2(p0, p1, lo[0], lo[1]);
        hh.y = packh_hi2(p2, p3, lo[2], lo[3]);
        hh.z = packh_hi2(p4, p5, lo[4], lo[5]);
        hh.w = packh_hi2(p6, p7, lo[6], lo[7]);
        ll.x = packh2(lo[0], lo[1]); ll.y = packh2(lo[2], lo[3]);
        ll.z = packh2(lo[4], lo[5]); ll.w = packh2(lo[6], lo[7]);
        *reinterpret_cast<uint4*>(prh + j0) = hh;
        *reinterpret_cast<uint4*>(prl + j0) = ll;
    }
}

// ---------------- gating -> fp16 hi/lo planes ----------------
__global__ void gate_kernel(const float* __restrict__ attn, const float* __restrict__ qkv,
                            __half* __restrict__ gh, __half* __restrict__ gl)
{
    size_t idx = (size_t)blockIdx.x * blockDim.x + threadIdx.x;
    if (idx >= (size_t)SEQ * NH * HD / 4) return;
    int s = (int)(idx >> 10);
    int r = (int)(idx & 1023);
    int h = r >> 6, dq = (r & 63) * 4;
    float4 a = *reinterpret_cast<const float4*>(&attn[((size_t)h * SEQ + s) * HD + dq]);
    float4 g = *reinterpret_cast<const float4*>(&qkv[(size_t)s * NQKV + h * 512 + 256 + dq]);
    float o0 = a.x * (1.f / (1.f + __expf(-g.x)));
    float o1 = a.y * (1.f / (1.f + __expf(-g.y)));
    float o2 = a.z * (1.f / (1.f + __expf(-g.z)));
    float o3 = a.w * (1.f / (1.f + __expf(-g.w)));
    float l0, l1, l2, l3;
    uint2 hh = { packh_hi2(o0, o1, l0, l1), packh_hi2(o2, o3, l2, l3) };
    uint2 ll = { packh2(l0, l1), packh2(l2, l3) };
    size_t o = (size_t)s * (NH * HD) + h * HD + dq;
    *reinterpret_cast<uint2*>(gh + o) = hh;
    *reinterpret_cast<uint2*>(gl + o) = ll;
}

// ---------------- launch ----------------
extern "C" void kernel_launch(void* const* d_in, const int* in_sizes, int n_in,
                              void* d_out, int out_size)
{
    const float* hidden = (const float*)d_in[0];
    const float* cosb   = (const float*)d_in[1];
    const float* sinb   = (const float*)d_in[2];
    const float* q_w    = (const float*)d_in[3];
    const float* k_w    = (const float*)d_in[4];
    const float* v_w    = (const float*)d_in[5];
    const float* o_w    = (const float*)d_in[6];
    const float* qnw    = (const float*)d_in[7];
    const float* knw    = (const float*)d_in[8];

    float* hidden_out = (float*)d_out;
    float* kcache = hidden_out + (size_t)SEQ * HID;
    float* vcache = kcache + (size_t)NKV * MAXS * HD;

    float *qkv, *sc, *at;
    __half *hidh, *hidl, *wqkv, *owh, *vT, *ph, *pl, *gth, *gtl;
    bf16 *qh, *ql, *kh, *kl;
    cudaGetSymbolAddress((void**)&qkv, g_qkv);
    cudaGetSymbolAddress((void**)&sc, g_scores);
    cudaGetSymbolAddress((void**)&at, g_attn);
    cudaGetSymbolAddress((void**)&hidh, g_hid_h); cudaGetSymbolAddress((void**)&hidl, g_hid_l);
    cudaGetSymbolAddress((void**)&wqkv, g_wqkv);
    cudaGetSymbolAddress((void**)&owh, g_ow);
    cudaGetSymbolAddress((void**)&qh, g_q_h);     cudaGetSymbolAddress((void**)&ql, g_q_l);
    cudaGetSymbolAddress((void**)&kh, g_k_h);     cudaGetSymbolAddress((void**)&kl, g_k_l);
    cudaGetSymbolAddress((void**)&vT, g_vT);
    cudaGetSymbolAddress((void**)&ph, g_p_h);     cudaGetSymbolAddress((void**)&pl, g_p_l);
    cudaGetSymbolAddress((void**)&gth, g_gt_h);   cudaGetSymbolAddress((void**)&gtl, g_gt_l);

    cudaFuncSetAttribute(gemm_hmma,      cudaFuncAttributeMaxDynamicSharedMemorySize, 196608);
    cudaFuncSetAttribute(gemm_hmma_wide, cudaFuncAttributeMaxDynamicSharedMemorySize, 196608);

    dim3 blk(256);
    dim3 gblk(512);

    // 1) cache zero-pad
    zero_pad_kernel<<<(unsigned)(((size_t)NKV * (MAXS - SEQ) * HD + 255) / 256), blk>>>(kcache, vcache);
    // 2) weight split
    split_w_kernel<<<26624, blk>>>(q_w, k_w, v_w, o_w, wqkv, owh);
    // 3) activation split
    split_a_kernel<<<4096, blk>>>(hidden, hidh, hidl);

    // 4) fused qkv projection [2048 x 9216], fp16 2-term wide
    gemm_hmma_wide<<<dim3(NQKV/256, SEQ/128, 1), gblk, 196608>>>(
        (const uint16_t*)hidh, (const uint16_t*)hidl, (const uint16_t*)wqkv,
        qkv, HID, HID, HID, NQKV, 0, 0, 0, 1, 1.f, 0);

    // 5-6) norms + rope + caches
    q_norm_rope_kernel<<<dim3(SEQ, NH), blk>>>(qkv, cosb, sinb, qnw, qh, ql);
    kv_norm_rope_kernel<<<dim3(SEQ, NKV), blk>>>(qkv, cosb, sinb, knw,
                                                 kcache, vcache, kh, kl, vT);

    // 7) scores = Q @ K^T * scale (causal block skip), bf16 3-term
    gemm_hmma<<<dim3(SEQ/128, SEQ/128, NH), gblk, 196608>>>(
        (const uint16_t*)qh, (const uint16_t*)ql, (const uint16_t*)kh, (const uint16_t*)kl,
        sc, HD, HD, HD, SEQ,
        (long long)SEQ * HD, (long long)SEQ * HD, (long long)SEQ * SEQ, GROUPS,
        ATT_SCALE, 1);

    // 8) softmax -> fp16 P planes
    softmax_kernel<<<dim3(SEQ, NH), blk>>>(sc, ph, pl);

    // 9) attn = P @ V (causal K limit), fp16 2-term wide
    gemm_hmma_wide<<<dim3(HD/256, SEQ/128, NH), gblk, 196608>>>(
        (const uint16_t*)ph, (const uint16_t*)pl, (const uint16_t*)vT,
        at, SEQ, SEQ, SEQ, HD,
        (long long)SEQ * SEQ, (long long)HD * SEQ, (long long)SEQ * HD, GROUPS,
        1.f, 2);

    // 10) gating -> fp16 planes
    gate_kernel<<<(unsigned)(((size_t)SEQ * NH * HD / 4 + 255) / 256), blk>>>(at, qkv, gth, gtl);

    // 11) hidden_out = gated @ o_w^T, fp16 2-term wide
    gemm_hmma_wide<<<dim3(HID/256, SEQ/128, 1), gblk, 196608>>>(
        (const uint16_t*)gth, (const uint16_t*)gtl, (const uint16_t*)owh,
        hidden_out, NH*HD, NH*HD, NH*HD, HID, 0, 0, 0, 1, 1.f, 0);
}